// round 14
// baseline (speedup 1.0000x reference)
#include <cuda_runtime.h>
#include <cuda_fp16.h>
#include <stdint.h>
#include <math.h>

#define B 4
#define S 2048
#define H 768
#define NH 12
#define HD 64
#define E 8
#define TOPK 2
#define F 3072
#define T (B*S)      /* 8192 tokens */
#define H3 (3*H)     /* 2304 */

// ---------------- scratch (device globals: no runtime allocation) ----------
__device__ __half g_qkv[(size_t)T*H3];     // fp16 QKV (GEMM writes fp16 directly)
__device__ __half g_qTh[(size_t)T*H];      // [bh][S][HD] fp16, pre-scaled 1/8
__device__ __half g_kTh[(size_t)T*H];      // [bh][S][HD] fp16
__device__ __half g_vTh[(size_t)T*H];      // [bh][HD][S] fp16 (transposed per head)
__device__ __half g_xt[(size_t)T*H];
__device__ __half g_ctx[(size_t)T*H];
__device__ float  g_attn[(size_t)T*H];
__device__ float  g_x1[(size_t)T*H];
__device__ __half g_x1t[(size_t)T*H];
__device__ __half g_hmid[(size_t)E*T*F];
__device__ float  g_ybuf[(size_t)E*T*H];
__device__ __half g_qkvwT[(size_t)H3*H];
__device__ __half g_outwT[(size_t)H*H];
__device__ __half g_w1T[(size_t)E*F*H];
__device__ __half g_w2T[(size_t)E*H*F];
__device__ int    g_cnt[E];
__device__ float  g_probsum[E];
__device__ int    g_tok[E*T];
__device__ int    g_slot[T*TOPK];
__device__ float  g_slotw[T*TOPK];

__global__ void zero_small() {
    if (threadIdx.x < E) { g_cnt[threadIdx.x] = 0; g_probsum[threadIdx.x] = 0.f; }
}

#define MMA_F16(d0,d1,d2,d3,a0,a1,a2,a3,b0,b1) \
    asm volatile("mma.sync.aligned.m16n8k16.row.col.f32.f16.f16.f32 " \
                 "{%0,%1,%2,%3},{%4,%5,%6,%7},{%8,%9},{%0,%1,%2,%3};" \
                 : "+f"(d0), "+f"(d1), "+f"(d2), "+f"(d3) \
                 : "r"(a0), "r"(a1), "r"(a2), "r"(a3), "r"(b0), "r"(b1))

__device__ __forceinline__ void cp_async16(void* smem_dst, const void* gsrc) {
    uint32_t saddr = (uint32_t)__cvta_generic_to_shared(smem_dst);
    asm volatile("cp.async.ca.shared.global [%0], [%1], 16;" :: "r"(saddr), "l"(gsrc));
}
#define CP_COMMIT asm volatile("cp.async.commit_group;")
#define CP_WAIT0  asm volatile("cp.async.wait_group 0;")
#define CP_WAIT1  asm volatile("cp.async.wait_group 1;")

__device__ __forceinline__ uint32_t h2_u32(float a, float b) {
    __half2 h = __floats2half2_rn(a, b);
    return *(uint32_t*)&h;
}

// ---------------- producers -------------------------------------------------
__global__ void half_copy(const float* __restrict__ src, __half* __restrict__ dst, int n) {
    int i = blockIdx.x * blockDim.x + threadIdx.x;
    if (i < n) dst[i] = __float2half_rn(src[i]);
}

__global__ void transpose_half(const float* __restrict__ src, __half* __restrict__ dst,
                               int R, int C) {
    __shared__ float tile[32][33];
    int e = blockIdx.z;
    src += (size_t)e * R * C;
    dst += (size_t)e * R * C;
    int c0 = blockIdx.x * 32, r0 = blockIdx.y * 32;
    int tx = threadIdx.x, ty0 = threadIdx.y;
    for (int ty = ty0; ty < 32; ty += 8)
        tile[ty][tx] = src[(size_t)(r0 + ty) * C + c0 + tx];
    __syncthreads();
    for (int ty = ty0; ty < 32; ty += 8)
        dst[(size_t)(c0 + ty) * R + r0 + tx] = __float2half_rn(tile[tx][ty]);
}

// V transpose: g_qkv(fp16) V slice -> g_vTh [(b*NH+h)*HD + d][S]
__global__ void vtrans_kernel() {
    __shared__ __half tile[32][34];
    int bh = blockIdx.z;
    int b = bh / NH, h = bh % NH;
    int s0 = blockIdx.x * 32, d0 = blockIdx.y * 32;
    int tx = threadIdx.x, ty0 = threadIdx.y;
    const __half* src = g_qkv + (size_t)b * S * H3 + (size_t)h * 192 + 128;
    for (int ty = ty0; ty < 32; ty += 8)
        tile[ty][tx] = src[(size_t)(s0 + ty) * H3 + d0 + tx];
    __syncthreads();
    __half* dst = g_vTh + ((size_t)bh * HD) * S;
    for (int ty = ty0; ty < 32; ty += 8)
        dst[(size_t)(d0 + ty) * S + s0 + tx] = tile[tx][ty];
}

// ---------------- fp16 tensor-core GEMM: 128x256 block, 64x64 warp ---------
// MODE 0: fp32 out. MODE 1: gather+GELU -> g_hmid fp16. MODE 2: expert-local
// A -> g_ybuf fp32. MODE 3: fp16 out (QKV).
#define BM 128
#define BN 256
#define BK 32
#define ASTR 40
#define GEMM_SMEM (3 * (BM*ASTR + BN*ASTR) * 2)   /* 92160 B */

template<int MODE>
__global__ void __launch_bounds__(256) gemm_f16(
    const __half* __restrict__ A, const __half* __restrict__ WT,
    void* __restrict__ CoutV, int M, int N, int K)
{
    extern __shared__ __half hsm[];
    __half* AsP = hsm;                        // [3][BM][ASTR]
    __half* BsP = hsm + 3 * BM * ASTR;        // [3][BN][ASTR]
    __shared__ int rt_s[BM];

    int e = blockIdx.z;
    int c = M;
    int r0 = blockIdx.y * BM;
    if (MODE == 1 || MODE == 2) {
        c = g_cnt[e];
        if (r0 >= c) return;
    }
    int col0 = blockIdx.x * BN;
    int tid = threadIdx.x;

    const __half* Ab = A;
    const __half* Wb = WT;
    if (MODE == 1) { Wb = WT + (size_t)e * N * K; }
    if (MODE == 2) { Ab = A + (size_t)e * T * K; Wb = WT + (size_t)e * N * K; }

    if (MODE == 1) {
        if (tid < BM) {
            int r = r0 + tid;
            rt_s[tid] = (r < c) ? g_tok[e * T + r] : 0;
        }
        __syncthreads();
    }

    int lane = tid & 31, warp = tid >> 5;
    int wm = warp >> 2, wn = warp & 3;
    int g = lane >> 2, cq = lane & 3;

    auto issueA = [&](int stage, int k0) {
        __half* dst = AsP + stage * BM * ASTR;
#pragma unroll
        for (int i = 0; i < 2; i++) {
            int lin = tid + i * 256;
            int r = lin >> 2, ch = lin & 3;
            const __half* src;
            if (MODE == 1) src = Ab + (size_t)rt_s[r] * K + k0 + ch * 8;
            else           src = Ab + (size_t)(r0 + r) * K + k0 + ch * 8;
            cp_async16(dst + r * ASTR + ch * 8, src);
        }
    };
    auto issueB = [&](int stage, int k0) {
        __half* dst = BsP + stage * BN * ASTR;
#pragma unroll
        for (int i = 0; i < 4; i++) {
            int lin = tid + i * 256;
            int r = lin >> 2, ch = lin & 3;
            cp_async16(dst + r * ASTR + ch * 8, Wb + (size_t)(col0 + r) * K + k0 + ch * 8);
        }
    };

    float acc[4][8][4];
#pragma unroll
    for (int i = 0; i < 4; i++)
#pragma unroll
        for (int j = 0; j < 8; j++)
#pragma unroll
            for (int k = 0; k < 4; k++) acc[i][j][k] = 0.f;

    int nIter = K / BK;
    issueA(0, 0); issueB(0, 0); CP_COMMIT;
    issueA(1, BK); issueB(1, BK); CP_COMMIT;
    int cur = 0;

    for (int it = 0; it < nIter; it++) {
        if (it < nIter - 1) { CP_WAIT1; } else { CP_WAIT0; }
        __syncthreads();
        if (it + 2 < nIter) {
            int st = (it + 2) % 3;
            issueA(st, (it + 2) * BK);
            issueB(st, (it + 2) * BK);
            CP_COMMIT;
        }
        const __half* Ac = AsP + cur * BM * ASTR;
        const __half* Bc = BsP + cur * BN * ASTR;
#pragma unroll
        for (int kk = 0; kk < BK; kk += 16) {
            uint32_t a[4][4], b[8][2];
#pragma unroll
            for (int mt = 0; mt < 4; mt++) {
                int m0 = wm * 64 + mt * 16;
                a[mt][0] = *(const uint32_t*)(Ac + (m0 + g    ) * ASTR + kk + 2 * cq);
                a[mt][1] = *(const uint32_t*)(Ac + (m0 + g + 8) * ASTR + kk + 2 * cq);
                a[mt][2] = *(const uint32_t*)(Ac + (m0 + g    ) * ASTR + kk + 2 * cq + 8);
                a[mt][3] = *(const uint32_t*)(Ac + (m0 + g + 8) * ASTR + kk + 2 * cq + 8);
            }
#pragma unroll
            for (int nt = 0; nt < 8; nt++) {
                int n0 = wn * 64 + nt * 8;
                b[nt][0] = *(const uint32_t*)(Bc + (n0 + g) * ASTR + kk + 2 * cq);
                b[nt][1] = *(const uint32_t*)(Bc + (n0 + g) * ASTR + kk + 2 * cq + 8);
            }
#pragma unroll
            for (int mt = 0; mt < 4; mt++)
#pragma unroll
                for (int nt = 0; nt < 8; nt++) {
                    MMA_F16(acc[mt][nt][0], acc[mt][nt][1], acc[mt][nt][2], acc[mt][nt][3],
                            a[mt][0], a[mt][1], a[mt][2], a[mt][3],
                            b[nt][0], b[nt][1]);
                }
        }
        cur = (cur + 1) % 3;
    }

    float* Cf = (float*)CoutV;
    __half* Ch = (__half*)CoutV;
#pragma unroll
    for (int mt = 0; mt < 4; mt++) {
#pragma unroll
        for (int nt = 0; nt < 8; nt++) {
#pragma unroll
            for (int hf = 0; hf < 2; hf++) {
                int lrow = wm * 64 + mt * 16 + g + hf * 8;
                int col = col0 + wn * 64 + nt * 8 + cq * 2;
                float v0 = acc[mt][nt][hf * 2 + 0];
                float v1 = acc[mt][nt][hf * 2 + 1];
                if (MODE == 0) {
                    Cf[(size_t)(r0 + lrow) * N + col]     = v0;
                    Cf[(size_t)(r0 + lrow) * N + col + 1] = v1;
                } else if (MODE == 3) {
                    Ch[(size_t)(r0 + lrow) * N + col]     = __float2half_rn(v0);
                    Ch[(size_t)(r0 + lrow) * N + col + 1] = __float2half_rn(v1);
                } else if (MODE == 1) {
                    int r = r0 + lrow;
                    if (r < c) {
                        float g0 = 0.5f * v0 * (1.f + erff(v0 * 0.70710678118f));
                        float g1 = 0.5f * v1 * (1.f + erff(v1 * 0.70710678118f));
                        g_hmid[((size_t)e * T + r) * F + col]     = __float2half_rn(g0);
                        g_hmid[((size_t)e * T + r) * F + col + 1] = __float2half_rn(g1);
                    }
                } else {
                    int r = r0 + lrow;
                    if (r < c) {
                        g_ybuf[((size_t)e * T + r) * H + col]     = v0;
                        g_ybuf[((size_t)e * T + r) * H + col + 1] = v1;
                    }
                }
            }
        }
    }
}

// ---------------- RoPE (reads fp16 qkv) -> fp16 Q (scaled), K --------------
__global__ void rope2_kernel() {
    int idx = blockIdx.x * blockDim.x + threadIdx.x;
    if (idx >= T * NH * 32) return;
    int i = idx & 31;
    int h = (idx >> 5) % NH;
    int t = idx / (32 * NH);
    int b = t / S, s = t % S;
    float invf = expf(-(float)i * (9.210340371976184f / 32.f));
    float th = (float)s * invf;
    float c = cosf(th), sn = sinf(th);
    const __half* p = g_qkv + (size_t)t * H3 + h * 192;
    size_t dbase = ((size_t)(b * NH + h) * S + s) * HD;
    float q1 = __half2float(p[i]), q2 = __half2float(p[i + 32]);
    g_qTh[dbase + i]      = __float2half_rn((q1 * c - q2 * sn) * 0.125f);
    g_qTh[dbase + i + 32] = __float2half_rn((q2 * c + q1 * sn) * 0.125f);
    float k1 = __half2float(p[64 + i]), k2 = __half2float(p[64 + i + 32]);
    g_kTh[dbase + i]      = __float2half_rn(k1 * c - k2 * sn);
    g_kTh[dbase + i + 32] = __float2half_rn(k2 * c + k1 * sn);
}

// ---------------- flash attention v6: full fp16 MMA, P in registers --------
#define KSH 72
#define VSH 72
#define FLASH_SMEM ((2*64*KSH + 2*64*VSH) * 2 + 2 * 64 * 4)

__global__ void __launch_bounds__(256) flash6_kernel(const int* __restrict__ mask) {
    extern __shared__ __half hfs[];
    __half* Kb = hfs;                          // [2][64][KSH]
    __half* Vb = Kb + 2 * 64 * KSH;            // [2][64][VSH] (V^T: row=dim)
    int*    Mb = (int*)(Vb + 2 * 64 * VSH);    // [2][64]

    int tid = threadIdx.x;
    int lane = tid & 31, warp = tid >> 5;
    int g = lane >> 2, cq = lane & 3;
    int q0 = blockIdx.x * 128, h = blockIdx.y, b = blockIdx.z;
    size_t bh = (size_t)(b * NH + h) * S;

    uint32_t qf[4][4];
    {
        const __half* qr0 = g_qTh + (bh + q0 + warp * 16 + g) * HD;
        const __half* qr1 = qr0 + 8 * HD;
#pragma unroll
        for (int cc = 0; cc < 4; cc++) {
            qf[cc][0] = *(const uint32_t*)(qr0 + cc * 16 + 2 * cq);
            qf[cc][1] = *(const uint32_t*)(qr1 + cc * 16 + 2 * cq);
            qf[cc][2] = *(const uint32_t*)(qr0 + cc * 16 + 2 * cq + 8);
            qf[cc][3] = *(const uint32_t*)(qr1 + cc * 16 + 2 * cq + 8);
        }
    }

    auto issueKV = [&](int buf, int k0) {
#pragma unroll
        for (int i = 0; i < 4; i++) {
            int lin = tid + i * 256;
            int row = lin >> 3, ch = lin & 7;
            if (row < 64) {
                const __half* src = g_kTh + (bh + k0 + row) * HD + ch * 8;
                cp_async16(Kb + buf * 64 * KSH + row * KSH + ch * 8, src);
            } else {
                int d = row - 64;
                const __half* src = g_vTh + ((size_t)(b * NH + h) * HD + d) * S + k0 + ch * 8;
                cp_async16(Vb + buf * 64 * VSH + d * VSH + ch * 8, src);
            }
        }
        if (tid < 16)
            cp_async16(Mb + buf * 64 + tid * 4, mask + b * S + k0 + tid * 4);
    };

    float acc_o[8][4];
#pragma unroll
    for (int nt = 0; nt < 8; nt++)
#pragma unroll
        for (int j = 0; j < 4; j++) acc_o[nt][j] = 0.f;
    float m0r = -1e30f, m1r = -1e30f, l0 = 0.f, l1 = 0.f;

    uint32_t fullm = 0xffffffffu;

    issueKV(0, 0);
    CP_COMMIT;
    int cur = 0;

    for (int k0 = 0; k0 < S; k0 += 64) {
        CP_WAIT0;
        __syncthreads();
        if (k0 + 64 < S) {
            issueKV(cur ^ 1, k0 + 64);
            CP_COMMIT;
        }
        const __half* Kc = Kb + cur * 64 * KSH;
        const __half* Vc = Vb + cur * 64 * VSH;
        const int*    Mc = Mb + cur * 64;

        float sacc[8][4];
#pragma unroll
        for (int nt = 0; nt < 8; nt++)
#pragma unroll
            for (int j = 0; j < 4; j++) sacc[nt][j] = 0.f;
#pragma unroll
        for (int cc = 0; cc < 4; cc++) {
            int kk = cc * 16;
#pragma unroll
            for (int nt = 0; nt < 8; nt++) {
                uint32_t b0 = *(const uint32_t*)(Kc + (nt * 8 + g) * KSH + kk + 2 * cq);
                uint32_t b1 = *(const uint32_t*)(Kc + (nt * 8 + g) * KSH + kk + 2 * cq + 8);
                MMA_F16(sacc[nt][0], sacc[nt][1], sacc[nt][2], sacc[nt][3],
                        qf[cc][0], qf[cc][1], qf[cc][2], qf[cc][3], b0, b1);
            }
        }

        float mx0 = -1e30f, mx1 = -1e30f;
#pragma unroll
        for (int nt = 0; nt < 8; nt++) {
            float mk0 = (Mc[nt * 8 + cq * 2]     == 0) ? -1e30f : 0.f;
            float mk1 = (Mc[nt * 8 + cq * 2 + 1] == 0) ? -1e30f : 0.f;
            sacc[nt][0] += mk0; sacc[nt][1] += mk1;
            sacc[nt][2] += mk0; sacc[nt][3] += mk1;
            mx0 = fmaxf(mx0, fmaxf(sacc[nt][0], sacc[nt][1]));
            mx1 = fmaxf(mx1, fmaxf(sacc[nt][2], sacc[nt][3]));
        }
        mx0 = fmaxf(mx0, __shfl_xor_sync(fullm, mx0, 1));
        mx0 = fmaxf(mx0, __shfl_xor_sync(fullm, mx0, 2));
        mx1 = fmaxf(mx1, __shfl_xor_sync(fullm, mx1, 1));
        mx1 = fmaxf(mx1, __shfl_xor_sync(fullm, mx1, 2));
        float newm0 = fmaxf(m0r, mx0), newm1 = fmaxf(m1r, mx1);
        float sc0 = __expf(m0r - newm0), sc1 = __expf(m1r - newm1);
        m0r = newm0; m1r = newm1;
        float ps0 = 0.f, ps1 = 0.f;
#pragma unroll
        for (int nt = 0; nt < 8; nt++) {
            sacc[nt][0] = __expf(sacc[nt][0] - newm0);
            sacc[nt][1] = __expf(sacc[nt][1] - newm0);
            sacc[nt][2] = __expf(sacc[nt][2] - newm1);
            sacc[nt][3] = __expf(sacc[nt][3] - newm1);
            ps0 += sacc[nt][0] + sacc[nt][1];
            ps1 += sacc[nt][2] + sacc[nt][3];
            acc_o[nt][0] *= sc0; acc_o[nt][1] *= sc0;
            acc_o[nt][2] *= sc1; acc_o[nt][3] *= sc1;
        }
        ps0 += __shfl_xor_sync(fullm, ps0, 1); ps0 += __shfl_xor_sync(fullm, ps0, 2);
        ps1 += __shfl_xor_sync(fullm, ps1, 1); ps1 += __shfl_xor_sync(fullm, ps1, 2);
        l0 = l0 * sc0 + ps0;
        l1 = l1 * sc1 + ps1;

#pragma unroll
        for (int kt = 0; kt < 4; kt++) {
            uint32_t a0 = h2_u32(sacc[2*kt][0],   sacc[2*kt][1]);
            uint32_t a1 = h2_u32(sacc[2*kt][2],   sacc[2*kt][3]);
            uint32_t a2 = h2_u32(sacc[2*kt+1][0], sacc[2*kt+1][1]);
            uint32_t a3 = h2_u32(sacc[2*kt+1][2], sacc[2*kt+1][3]);
            int kk = kt * 16;
#pragma unroll
            for (int nt = 0; nt < 8; nt++) {
                uint32_t b0 = *(const uint32_t*)(Vc + (nt * 8 + g) * VSH + kk + 2 * cq);
                uint32_t b1 = *(const uint32_t*)(Vc + (nt * 8 + g) * VSH + kk + 2 * cq + 8);
                MMA_F16(acc_o[nt][0], acc_o[nt][1], acc_o[nt][2], acc_o[nt][3],
                        a0, a1, a2, a3, b0, b1);
            }
        }
        cur ^= 1;
    }

    float inv0 = 1.f / l0, inv1 = 1.f / l1;
    size_t row0 = (size_t)(b * S + q0 + warp * 16 + g) * H + h * HD;
    size_t row1 = row0 + (size_t)8 * H;
#pragma unroll
    for (int nt = 0; nt < 8; nt++) {
        int col = nt * 8 + cq * 2;
        g_ctx[row0 + col]     = __float2half_rn(acc_o[nt][0] * inv0);
        g_ctx[row0 + col + 1] = __float2half_rn(acc_o[nt][1] * inv0);
        g_ctx[row1 + col]     = __float2half_rn(acc_o[nt][2] * inv1);
        g_ctx[row1 + col + 1] = __float2half_rn(acc_o[nt][3] * inv1);
    }
}

// ---------------- residual add + RMSNorm (+ fp16 copy) ---------------------
__global__ void addnorm_kernel(const float* __restrict__ a, const float* __restrict__ bb,
                               const float* __restrict__ w, float* __restrict__ out,
                               __half* __restrict__ out_h) {
    __shared__ float buf[H];
    __shared__ float red[8];
    int t = blockIdx.x, tid = threadIdx.x;
    float ss = 0.f;
    for (int d = tid; d < H; d += 256) {
        float v = a[(size_t)t * H + d] + bb[(size_t)t * H + d];
        buf[d] = v;
        ss += v * v;
    }
    for (int o = 16; o; o >>= 1) ss += __shfl_xor_sync(~0u, ss, o);
    if ((tid & 31) == 0) red[tid >> 5] = ss;
    __syncthreads();
    if (tid < 8) {
        float x = red[tid];
        for (int o = 4; o; o >>= 1) x += __shfl_xor_sync(0xffu, x, o);
        if (tid == 0) red[0] = x;
    }
    __syncthreads();
    float inv = rsqrtf(red[0] / (float)H + 1.1920929e-7f);
    for (int d = tid; d < H; d += 256) {
        float v = buf[d] * inv * w[d];
        out[(size_t)t * H + d] = v;
        if (out_h) out_h[(size_t)t * H + d] = __float2half_rn(v);
    }
}

// ---------------- MoE combine (slots) + residual + RMSNorm -----------------
__global__ void moe_combine_norm(const float* __restrict__ w, float* __restrict__ out) {
    __shared__ float buf[H];
    __shared__ float red[8];
    int t = blockIdx.x, tid = threadIdx.x;
    int s0 = g_slot[t * 2], s1 = g_slot[t * 2 + 1];
    float w0 = g_slotw[t * 2], w1v = g_slotw[t * 2 + 1];
    float ss = 0.f;
    for (int d = tid; d < H; d += 256) {
        float v = g_x1[(size_t)t * H + d]
                + w0 * g_ybuf[(size_t)s0 * H + d]
                + w1v * g_ybuf[(size_t)s1 * H + d];
        buf[d] = v;
        ss += v * v;
    }
    for (int o = 16; o; o >>= 1) ss += __shfl_xor_sync(~0u, ss, o);
    if ((tid & 31) == 0) red[tid >> 5] = ss;
    __syncthreads();
    if (tid < 8) {
        float x = red[tid];
        for (int o = 4; o; o >>= 1) x += __shfl_xor_sync(0xffu, x, o);
        if (tid == 0) red[0] = x;
    }
    __syncthreads();
    float inv = rsqrtf(red[0] / (float)H + 1.1920929e-7f);
    for (int d = tid; d < H; d += 256)
        out[(size_t)t * H + d] = buf[d] * inv * w[d];
}

// ---------------- router -----------------------------------------------------
__global__ void router_kernel(const float* __restrict__ gate_w) {
    int warp = threadIdx.x >> 5, lane = threadIdx.x & 31;
    int t = blockIdx.x * 8 + warp;
    float acc[E];
#pragma unroll
    for (int e = 0; e < E; e++) acc[e] = 0.f;
    const float* xr = g_x1 + (size_t)t * H;
    for (int d = lane; d < H; d += 32) {
        float xv = xr[d];
        const float* g = gate_w + (size_t)d * E;
#pragma unroll
        for (int e = 0; e < E; e++) acc[e] += xv * g[e];
    }
#pragma unroll
    for (int e = 0; e < E; e++)
        for (int o = 16; o; o >>= 1) acc[e] += __shfl_xor_sync(~0u, acc[e], o);
    if (lane == 0) {
        float mx = acc[0];
#pragma unroll
        for (int e = 1; e < E; e++) mx = fmaxf(mx, acc[e]);
        float p[E]; float sum = 0.f;
#pragma unroll
        for (int e = 0; e < E; e++) { p[e] = expf(acc[e] - mx); sum += p[e]; }
        float inv = 1.f / sum;
#pragma unroll
        for (int e = 0; e < E; e++) p[e] *= inv;
        int i1 = 0;
#pragma unroll
        for (int e = 1; e < E; e++) if (p[e] > p[i1]) i1 = e;
        int i2 = -1;
#pragma unroll
        for (int e = 0; e < E; e++) {
            if (e == i1) continue;
            if (i2 < 0 || p[e] > p[i2]) i2 = e;
        }
        float s2 = p[i1] + p[i2];
        float w1n = p[i1] / s2, w2n = p[i2] / s2;
        int pos = atomicAdd(&g_cnt[i1], 1);
        g_tok[i1 * T + pos] = t;
        g_slot[t * 2] = i1 * T + pos;
        g_slotw[t * 2] = w1n;
        pos = atomicAdd(&g_cnt[i2], 1);
        g_tok[i2 * T + pos] = t;
        g_slot[t * 2 + 1] = i2 * T + pos;
        g_slotw[t * 2 + 1] = w2n;
#pragma unroll
        for (int e = 0; e < E; e++) atomicAdd(&g_probsum[e], p[e]);
    }
}

__global__ void aux_kernel(float* out) {
    float a = 0.f;
    for (int e = 0; e < E; e++)
        a += ((float)g_cnt[e] / (float)T) * (g_probsum[e] / (float)T);
    out[0] = (float)E * a;
}

// ---------------------------------------------------------------------------
extern "C" void kernel_launch(void* const* d_in, const int* in_sizes, int n_in,
                              void* d_out, int out_size) {
    const float* x      = (const float*)d_in[0];
    const int*   mask   = (const int*)  d_in[1];
    const float* qkv_w  = (const float*)d_in[2];
    const float* out_w  = (const float*)d_in[3];
    const float* gate_w = (const float*)d_in[4];
    const float* w1     = (const float*)d_in[5];
    const float* w2     = (const float*)d_in[6];
    const float* n1     = (const float*)d_in[7];
    const float* n2     = (const float*)d_in[8];
    float* out = (float*)d_out;

    float *p_attn, *p_x1;
    __half *p_qkv, *p_xt, *p_ctx, *p_x1t, *p_hmid;
    __half *p_qkvwT, *p_outwT, *p_w1T, *p_w2T;
    cudaGetSymbolAddress((void**)&p_qkv,   g_qkv);
    cudaGetSymbolAddress((void**)&p_ctx,   g_ctx);
    cudaGetSymbolAddress((void**)&p_attn,  g_attn);
    cudaGetSymbolAddress((void**)&p_x1,    g_x1);
    cudaGetSymbolAddress((void**)&p_x1t,   g_x1t);
    cudaGetSymbolAddress((void**)&p_xt,    g_xt);
    cudaGetSymbolAddress((void**)&p_hmid,  g_hmid);
    cudaGetSymbolAddress((void**)&p_qkvwT, g_qkvwT);
    cudaGetSymbolAddress((void**)&p_outwT, g_outwT);
    cudaGetSymbolAddress((void**)&p_w1T,   g_w1T);
    cudaGetSymbolAddress((void**)&p_w2T,   g_w2T);

    static bool attr_set = false;
    if (!attr_set) {
        cudaFuncSetAttribute(flash6_kernel,
                             cudaFuncAttributeMaxDynamicSharedMemorySize, FLASH_SMEM);
        cudaFuncSetAttribute(gemm_f16<0>,
                             cudaFuncAttributeMaxDynamicSharedMemorySize, GEMM_SMEM);
        cudaFuncSetAttribute(gemm_f16<1>,
                             cudaFuncAttributeMaxDynamicSharedMemorySize, GEMM_SMEM);
        cudaFuncSetAttribute(gemm_f16<2>,
                             cudaFuncAttributeMaxDynamicSharedMemorySize, GEMM_SMEM);
        cudaFuncSetAttribute(gemm_f16<3>,
                             cudaFuncAttributeMaxDynamicSharedMemorySize, GEMM_SMEM);
        attr_set = true;
    }

    zero_small<<<1, 32>>>();

    half_copy<<<(T * H + 255) / 256, 256>>>(x, p_xt, T * H);
    transpose_half<<<dim3(H3 / 32, H / 32, 1), dim3(32, 8)>>>(qkv_w, p_qkvwT, H, H3);
    transpose_half<<<dim3(H / 32, H / 32, 1),  dim3(32, 8)>>>(out_w, p_outwT, H, H);
    transpose_half<<<dim3(F / 32, H / 32, E),  dim3(32, 8)>>>(w1, p_w1T, H, F);
    transpose_half<<<dim3(H / 32, F / 32, E),  dim3(32, 8)>>>(w2, p_w2T, F, H);

    // QKV projection (fp16 out)
    gemm_f16<3><<<dim3(H3 / BN, T / BM, 1), 256, GEMM_SMEM>>>(p_xt, p_qkvwT, p_qkv, T, H3, H);

    rope2_kernel<<<(T * NH * 32 + 255) / 256, 256>>>();
    vtrans_kernel<<<dim3(S / 32, HD / 32, B * NH), dim3(32, 8)>>>();

    flash6_kernel<<<dim3(S / 128, NH, B), 256, FLASH_SMEM>>>(mask);

    // out projection (fp32 out)
    gemm_f16<0><<<dim3(H / BN, T / BM, 1), 256, GEMM_SMEM>>>(p_ctx, p_outwT, p_attn, T, H, H);

    addnorm_kernel<<<T, 256>>>(x, p_attn, n1, p_x1, p_x1t);

    router_kernel<<<T / 8, 256>>>(gate_w);
    aux_kernel<<<1, 1>>>(out + (size_t)T * H);

    gemm_f16<1><<<dim3(F / BN, T / BM, E), 256, GEMM_SMEM>>>(p_x1t, p_w1T, nullptr, T, F, H);
    gemm_f16<2><<<dim3(H / BN, T / BM, E), 256, GEMM_SMEM>>>(p_hmid, p_w2T, nullptr, T, H, F);

    moe_combine_norm<<<T, 256>>>(n2, out);
}

// round 15
// speedup vs baseline: 1.0205x; 1.0205x over previous
#include <cuda_runtime.h>
#include <cuda_fp16.h>
#include <stdint.h>
#include <math.h>

#define B 4
#define S 2048
#define H 768
#define NH 12
#define HD 64
#define E 8
#define TOPK 2
#define F 3072
#define T (B*S)      /* 8192 tokens */
#define H3 (3*H)     /* 2304 */

// ---------------- scratch (device globals: no runtime allocation) ----------
__device__ __half g_qkv[(size_t)T*H3];     // fp16 QKV (GEMM writes fp16 directly)
__device__ __half g_qTh[(size_t)T*H];      // [bh][S][HD] fp16, pre-scaled 1/8
__device__ __half g_kTh[(size_t)T*H];      // [bh][S][HD] fp16
__device__ __half g_vTh[(size_t)T*H];      // [bh][HD][S] fp16 (transposed per head)
__device__ __half g_xt[(size_t)T*H];
__device__ __half g_ctx[(size_t)T*H];
__device__ float  g_attn[(size_t)T*H];
__device__ float  g_x1[(size_t)T*H];
__device__ __half g_x1t[(size_t)T*H];
__device__ __half g_hmid[(size_t)E*T*F];
__device__ float  g_ybuf[(size_t)E*T*H];
__device__ __half g_qkvwT[(size_t)H3*H];
__device__ __half g_outwT[(size_t)H*H];
__device__ __half g_w1T[(size_t)E*F*H];
__device__ __half g_w2T[(size_t)E*H*F];
__device__ int    g_cnt[E];
__device__ float  g_probsum[E];
__device__ int    g_tok[E*T];
__device__ int    g_slot[T*TOPK];
__device__ float  g_slotw[T*TOPK];

__global__ void zero_small() {
    if (threadIdx.x < E) { g_cnt[threadIdx.x] = 0; g_probsum[threadIdx.x] = 0.f; }
}

#define MMA_F16(d0,d1,d2,d3,a0,a1,a2,a3,b0,b1) \
    asm volatile("mma.sync.aligned.m16n8k16.row.col.f32.f16.f16.f32 " \
                 "{%0,%1,%2,%3},{%4,%5,%6,%7},{%8,%9},{%0,%1,%2,%3};" \
                 : "+f"(d0), "+f"(d1), "+f"(d2), "+f"(d3) \
                 : "r"(a0), "r"(a1), "r"(a2), "r"(a3), "r"(b0), "r"(b1))

__device__ __forceinline__ void cp_async16(void* smem_dst, const void* gsrc) {
    uint32_t saddr = (uint32_t)__cvta_generic_to_shared(smem_dst);
    asm volatile("cp.async.ca.shared.global [%0], [%1], 16;" :: "r"(saddr), "l"(gsrc));
}
#define CP_COMMIT asm volatile("cp.async.commit_group;")
#define CP_WAIT0  asm volatile("cp.async.wait_group 0;")
#define CP_WAIT1  asm volatile("cp.async.wait_group 1;")

__device__ __forceinline__ uint32_t h2_u32(float a, float b) {
    __half2 h = __floats2half2_rn(a, b);
    return *(uint32_t*)&h;
}

// ---------------- producers -------------------------------------------------
__global__ void half_copy(const float* __restrict__ src, __half* __restrict__ dst, int n) {
    int i = blockIdx.x * blockDim.x + threadIdx.x;
    if (i < n) dst[i] = __float2half_rn(src[i]);
}

__global__ void transpose_half(const float* __restrict__ src, __half* __restrict__ dst,
                               int R, int C) {
    __shared__ float tile[32][33];
    int e = blockIdx.z;
    src += (size_t)e * R * C;
    dst += (size_t)e * R * C;
    int c0 = blockIdx.x * 32, r0 = blockIdx.y * 32;
    int tx = threadIdx.x, ty0 = threadIdx.y;
    for (int ty = ty0; ty < 32; ty += 8)
        tile[ty][tx] = src[(size_t)(r0 + ty) * C + c0 + tx];
    __syncthreads();
    for (int ty = ty0; ty < 32; ty += 8)
        dst[(size_t)(c0 + ty) * R + r0 + tx] = __float2half_rn(tile[tx][ty]);
}

// V transpose: g_qkv(fp16) V slice -> g_vTh [(b*NH+h)*HD + d][S]
__global__ void vtrans_kernel() {
    __shared__ __half tile[32][34];
    int bh = blockIdx.z;
    int b = bh / NH, h = bh % NH;
    int s0 = blockIdx.x * 32, d0 = blockIdx.y * 32;
    int tx = threadIdx.x, ty0 = threadIdx.y;
    const __half* src = g_qkv + (size_t)b * S * H3 + (size_t)h * 192 + 128;
    for (int ty = ty0; ty < 32; ty += 8)
        tile[ty][tx] = src[(size_t)(s0 + ty) * H3 + d0 + tx];
    __syncthreads();
    __half* dst = g_vTh + ((size_t)bh * HD) * S;
    for (int ty = ty0; ty < 32; ty += 8)
        dst[(size_t)(d0 + ty) * S + s0 + tx] = tile[tx][ty];
}

// ---------------- fp16 tensor-core GEMM, 3-stage cp.async, 128x128 ---------
// MODE 0: fp32 out. MODE 1: gather+GELU -> g_hmid fp16. MODE 2: expert-local
// A -> g_ybuf fp32. MODE 3: fp16 out (QKV).
#define BM 128
#define BN 128
#define BK 32
#define ASTR 40
#define GEMM_SMEM (3 * (BM*ASTR + BN*ASTR) * 2)   /* 61440 B */

template<int MODE>
__global__ void __launch_bounds__(256) gemm_f16(
    const __half* __restrict__ A, const __half* __restrict__ WT,
    void* __restrict__ CoutV, int M, int N, int K)
{
    extern __shared__ __half hsm[];
    __half* AsP = hsm;                        // [3][BM][ASTR]
    __half* BsP = hsm + 3 * BM * ASTR;        // [3][BN][ASTR]
    __shared__ int rt_s[BM];

    int e = blockIdx.z;
    int c = M;
    int r0 = blockIdx.y * BM;
    if (MODE == 1 || MODE == 2) {
        c = g_cnt[e];
        if (r0 >= c) return;
    }
    int col0 = blockIdx.x * BN;
    int tid = threadIdx.x;

    const __half* Ab = A;
    const __half* Wb = WT;
    if (MODE == 1) { Wb = WT + (size_t)e * N * K; }
    if (MODE == 2) { Ab = A + (size_t)e * T * K; Wb = WT + (size_t)e * N * K; }

    if (MODE == 1) {
        if (tid < BM) {
            int r = r0 + tid;
            rt_s[tid] = (r < c) ? g_tok[e * T + r] : 0;
        }
        __syncthreads();
    }

    int lane = tid & 31, warp = tid >> 5;
    int wm = warp >> 2, wn = warp & 3;
    int g = lane >> 2, cq = lane & 3;

    auto issueA = [&](int stage, int k0) {
        __half* dst = AsP + stage * BM * ASTR;
#pragma unroll
        for (int i = 0; i < 2; i++) {
            int lin = tid + i * 256;
            int r = lin >> 2, ch = lin & 3;
            const __half* src;
            if (MODE == 1) src = Ab + (size_t)rt_s[r] * K + k0 + ch * 8;
            else           src = Ab + (size_t)(r0 + r) * K + k0 + ch * 8;
            cp_async16(dst + r * ASTR + ch * 8, src);
        }
    };
    auto issueB = [&](int stage, int k0) {
        __half* dst = BsP + stage * BN * ASTR;
#pragma unroll
        for (int i = 0; i < 2; i++) {
            int lin = tid + i * 256;
            int r = lin >> 2, ch = lin & 3;
            cp_async16(dst + r * ASTR + ch * 8, Wb + (size_t)(col0 + r) * K + k0 + ch * 8);
        }
    };

    float acc[4][4][4];
#pragma unroll
    for (int i = 0; i < 4; i++)
#pragma unroll
        for (int j = 0; j < 4; j++)
#pragma unroll
            for (int k = 0; k < 4; k++) acc[i][j][k] = 0.f;

    int nIter = K / BK;
    issueA(0, 0); issueB(0, 0); CP_COMMIT;
    issueA(1, BK); issueB(1, BK); CP_COMMIT;
    int cur = 0;

    for (int it = 0; it < nIter; it++) {
        if (it < nIter - 1) { CP_WAIT1; } else { CP_WAIT0; }
        __syncthreads();
        if (it + 2 < nIter) {
            int st = (it + 2) % 3;
            issueA(st, (it + 2) * BK);
            issueB(st, (it + 2) * BK);
            CP_COMMIT;
        }
        const __half* Ac = AsP + cur * BM * ASTR;
        const __half* Bc = BsP + cur * BN * ASTR;
#pragma unroll
        for (int kk = 0; kk < BK; kk += 16) {
            uint32_t a[4][4], b[4][2];
#pragma unroll
            for (int mt = 0; mt < 4; mt++) {
                int m0 = wm * 64 + mt * 16;
                a[mt][0] = *(const uint32_t*)(Ac + (m0 + g    ) * ASTR + kk + 2 * cq);
                a[mt][1] = *(const uint32_t*)(Ac + (m0 + g + 8) * ASTR + kk + 2 * cq);
                a[mt][2] = *(const uint32_t*)(Ac + (m0 + g    ) * ASTR + kk + 2 * cq + 8);
                a[mt][3] = *(const uint32_t*)(Ac + (m0 + g + 8) * ASTR + kk + 2 * cq + 8);
            }
#pragma unroll
            for (int nt = 0; nt < 4; nt++) {
                int n0 = wn * 32 + nt * 8;
                b[nt][0] = *(const uint32_t*)(Bc + (n0 + g) * ASTR + kk + 2 * cq);
                b[nt][1] = *(const uint32_t*)(Bc + (n0 + g) * ASTR + kk + 2 * cq + 8);
            }
#pragma unroll
            for (int mt = 0; mt < 4; mt++)
#pragma unroll
                for (int nt = 0; nt < 4; nt++) {
                    MMA_F16(acc[mt][nt][0], acc[mt][nt][1], acc[mt][nt][2], acc[mt][nt][3],
                            a[mt][0], a[mt][1], a[mt][2], a[mt][3],
                            b[nt][0], b[nt][1]);
                }
        }
        cur = (cur + 1) % 3;
    }

    float* Cf = (float*)CoutV;
    __half* Ch = (__half*)CoutV;
#pragma unroll
    for (int mt = 0; mt < 4; mt++) {
#pragma unroll
        for (int nt = 0; nt < 4; nt++) {
#pragma unroll
            for (int hf = 0; hf < 2; hf++) {
                int lrow = wm * 64 + mt * 16 + g + hf * 8;
                int col = col0 + wn * 32 + nt * 8 + cq * 2;
                float v0 = acc[mt][nt][hf * 2 + 0];
                float v1 = acc[mt][nt][hf * 2 + 1];
                if (MODE == 0) {
                    Cf[(size_t)(r0 + lrow) * N + col]     = v0;
                    Cf[(size_t)(r0 + lrow) * N + col + 1] = v1;
                } else if (MODE == 3) {
                    Ch[(size_t)(r0 + lrow) * N + col]     = __float2half_rn(v0);
                    Ch[(size_t)(r0 + lrow) * N + col + 1] = __float2half_rn(v1);
                } else if (MODE == 1) {
                    int r = r0 + lrow;
                    if (r < c) {
                        float g0 = 0.5f * v0 * (1.f + erff(v0 * 0.70710678118f));
                        float g1 = 0.5f * v1 * (1.f + erff(v1 * 0.70710678118f));
                        g_hmid[((size_t)e * T + r) * F + col]     = __float2half_rn(g0);
                        g_hmid[((size_t)e * T + r) * F + col + 1] = __float2half_rn(g1);
                    }
                } else {
                    int r = r0 + lrow;
                    if (r < c) {
                        g_ybuf[((size_t)e * T + r) * H + col]     = v0;
                        g_ybuf[((size_t)e * T + r) * H + col + 1] = v1;
                    }
                }
            }
        }
    }
}

// ---------------- RoPE (reads fp16 qkv) -> fp16 Q (scaled), K --------------
__global__ void rope2_kernel() {
    int idx = blockIdx.x * blockDim.x + threadIdx.x;
    if (idx >= T * NH * 32) return;
    int i = idx & 31;
    int h = (idx >> 5) % NH;
    int t = idx / (32 * NH);
    int b = t / S, s = t % S;
    float invf = expf(-(float)i * (9.210340371976184f / 32.f));
    float th = (float)s * invf;
    float c = cosf(th), sn = sinf(th);
    const __half* p = g_qkv + (size_t)t * H3 + h * 192;
    size_t dbase = ((size_t)(b * NH + h) * S + s) * HD;
    float q1 = __half2float(p[i]), q2 = __half2float(p[i + 32]);
    g_qTh[dbase + i]      = __float2half_rn((q1 * c - q2 * sn) * 0.125f);
    g_qTh[dbase + i + 32] = __float2half_rn((q2 * c + q1 * sn) * 0.125f);
    float k1 = __half2float(p[64 + i]), k2 = __half2float(p[64 + i + 32]);
    g_kTh[dbase + i]      = __float2half_rn(k1 * c - k2 * sn);
    g_kTh[dbase + i + 32] = __float2half_rn(k2 * c + k1 * sn);
}

// ---------------- flash attention v6: full fp16 MMA, P in registers --------
#define KSH 72
#define VSH 72
#define FLASH_SMEM ((2*64*KSH + 2*64*VSH) * 2 + 2 * 64 * 4)

__global__ void __launch_bounds__(256) flash6_kernel(const int* __restrict__ mask) {
    extern __shared__ __half hfs[];
    __half* Kb = hfs;                          // [2][64][KSH]
    __half* Vb = Kb + 2 * 64 * KSH;            // [2][64][VSH] (V^T: row=dim)
    int*    Mb = (int*)(Vb + 2 * 64 * VSH);    // [2][64]

    int tid = threadIdx.x;
    int lane = tid & 31, warp = tid >> 5;
    int g = lane >> 2, cq = lane & 3;
    int q0 = blockIdx.x * 128, h = blockIdx.y, b = blockIdx.z;
    size_t bh = (size_t)(b * NH + h) * S;

    uint32_t qf[4][4];
    {
        const __half* qr0 = g_qTh + (bh + q0 + warp * 16 + g) * HD;
        const __half* qr1 = qr0 + 8 * HD;
#pragma unroll
        for (int cc = 0; cc < 4; cc++) {
            qf[cc][0] = *(const uint32_t*)(qr0 + cc * 16 + 2 * cq);
            qf[cc][1] = *(const uint32_t*)(qr1 + cc * 16 + 2 * cq);
            qf[cc][2] = *(const uint32_t*)(qr0 + cc * 16 + 2 * cq + 8);
            qf[cc][3] = *(const uint32_t*)(qr1 + cc * 16 + 2 * cq + 8);
        }
    }

    auto issueKV = [&](int buf, int k0) {
#pragma unroll
        for (int i = 0; i < 4; i++) {
            int lin = tid + i * 256;
            int row = lin >> 3, ch = lin & 7;
            if (row < 64) {
                const __half* src = g_kTh + (bh + k0 + row) * HD + ch * 8;
                cp_async16(Kb + buf * 64 * KSH + row * KSH + ch * 8, src);
            } else {
                int d = row - 64;
                const __half* src = g_vTh + ((size_t)(b * NH + h) * HD + d) * S + k0 + ch * 8;
                cp_async16(Vb + buf * 64 * VSH + d * VSH + ch * 8, src);
            }
        }
        if (tid < 16)
            cp_async16(Mb + buf * 64 + tid * 4, mask + b * S + k0 + tid * 4);
    };

    float acc_o[8][4];
#pragma unroll
    for (int nt = 0; nt < 8; nt++)
#pragma unroll
        for (int j = 0; j < 4; j++) acc_o[nt][j] = 0.f;
    float m0r = -1e30f, m1r = -1e30f, l0 = 0.f, l1 = 0.f;

    uint32_t fullm = 0xffffffffu;

    issueKV(0, 0);
    CP_COMMIT;
    int cur = 0;

    for (int k0 = 0; k0 < S; k0 += 64) {
        CP_WAIT0;
        __syncthreads();
        if (k0 + 64 < S) {
            issueKV(cur ^ 1, k0 + 64);
            CP_COMMIT;
        }
        const __half* Kc = Kb + cur * 64 * KSH;
        const __half* Vc = Vb + cur * 64 * VSH;
        const int*    Mc = Mb + cur * 64;

        float sacc[8][4];
#pragma unroll
        for (int nt = 0; nt < 8; nt++)
#pragma unroll
            for (int j = 0; j < 4; j++) sacc[nt][j] = 0.f;
#pragma unroll
        for (int cc = 0; cc < 4; cc++) {
            int kk = cc * 16;
#pragma unroll
            for (int nt = 0; nt < 8; nt++) {
                uint32_t b0 = *(const uint32_t*)(Kc + (nt * 8 + g) * KSH + kk + 2 * cq);
                uint32_t b1 = *(const uint32_t*)(Kc + (nt * 8 + g) * KSH + kk + 2 * cq + 8);
                MMA_F16(sacc[nt][0], sacc[nt][1], sacc[nt][2], sacc[nt][3],
                        qf[cc][0], qf[cc][1], qf[cc][2], qf[cc][3], b0, b1);
            }
        }

        float mx0 = -1e30f, mx1 = -1e30f;
#pragma unroll
        for (int nt = 0; nt < 8; nt++) {
            float mk0 = (Mc[nt * 8 + cq * 2]     == 0) ? -1e30f : 0.f;
            float mk1 = (Mc[nt * 8 + cq * 2 + 1] == 0) ? -1e30f : 0.f;
            sacc[nt][0] += mk0; sacc[nt][1] += mk1;
            sacc[nt][2] += mk0; sacc[nt][3] += mk1;
            mx0 = fmaxf(mx0, fmaxf(sacc[nt][0], sacc[nt][1]));
            mx1 = fmaxf(mx1, fmaxf(sacc[nt][2], sacc[nt][3]));
        }
        mx0 = fmaxf(mx0, __shfl_xor_sync(fullm, mx0, 1));
        mx0 = fmaxf(mx0, __shfl_xor_sync(fullm, mx0, 2));
        mx1 = fmaxf(mx1, __shfl_xor_sync(fullm, mx1, 1));
        mx1 = fmaxf(mx1, __shfl_xor_sync(fullm, mx1, 2));
        float newm0 = fmaxf(m0r, mx0), newm1 = fmaxf(m1r, mx1);
        float sc0 = __expf(m0r - newm0), sc1 = __expf(m1r - newm1);
        m0r = newm0; m1r = newm1;
        float ps0 = 0.f, ps1 = 0.f;
#pragma unroll
        for (int nt = 0; nt < 8; nt++) {
            sacc[nt][0] = __expf(sacc[nt][0] - newm0);
            sacc[nt][1] = __expf(sacc[nt][1] - newm0);
            sacc[nt][2] = __expf(sacc[nt][2] - newm1);
            sacc[nt][3] = __expf(sacc[nt][3] - newm1);
            ps0 += sacc[nt][0] + sacc[nt][1];
            ps1 += sacc[nt][2] + sacc[nt][3];
            acc_o[nt][0] *= sc0; acc_o[nt][1] *= sc0;
            acc_o[nt][2] *= sc1; acc_o[nt][3] *= sc1;
        }
        ps0 += __shfl_xor_sync(fullm, ps0, 1); ps0 += __shfl_xor_sync(fullm, ps0, 2);
        ps1 += __shfl_xor_sync(fullm, ps1, 1); ps1 += __shfl_xor_sync(fullm, ps1, 2);
        l0 = l0 * sc0 + ps0;
        l1 = l1 * sc1 + ps1;

#pragma unroll
        for (int kt = 0; kt < 4; kt++) {
            uint32_t a0 = h2_u32(sacc[2*kt][0],   sacc[2*kt][1]);
            uint32_t a1 = h2_u32(sacc[2*kt][2],   sacc[2*kt][3]);
            uint32_t a2 = h2_u32(sacc[2*kt+1][0], sacc[2*kt+1][1]);
            uint32_t a3 = h2_u32(sacc[2*kt+1][2], sacc[2*kt+1][3]);
            int kk = kt * 16;
#pragma unroll
            for (int nt = 0; nt < 8; nt++) {
                uint32_t b0 = *(const uint32_t*)(Vc + (nt * 8 + g) * VSH + kk + 2 * cq);
                uint32_t b1 = *(const uint32_t*)(Vc + (nt * 8 + g) * VSH + kk + 2 * cq + 8);
                MMA_F16(acc_o[nt][0], acc_o[nt][1], acc_o[nt][2], acc_o[nt][3],
                        a0, a1, a2, a3, b0, b1);
            }
        }
        cur ^= 1;
    }

    float inv0 = 1.f / l0, inv1 = 1.f / l1;
    size_t row0 = (size_t)(b * S + q0 + warp * 16 + g) * H + h * HD;
    size_t row1 = row0 + (size_t)8 * H;
#pragma unroll
    for (int nt = 0; nt < 8; nt++) {
        int col = nt * 8 + cq * 2;
        g_ctx[row0 + col]     = __float2half_rn(acc_o[nt][0] * inv0);
        g_ctx[row0 + col + 1] = __float2half_rn(acc_o[nt][1] * inv0);
        g_ctx[row1 + col]     = __float2half_rn(acc_o[nt][2] * inv1);
        g_ctx[row1 + col + 1] = __float2half_rn(acc_o[nt][3] * inv1);
    }
}

// ---------------- residual add + RMSNorm (+ fp16 copy) ---------------------
__global__ void addnorm_kernel(const float* __restrict__ a, const float* __restrict__ bb,
                               const float* __restrict__ w, float* __restrict__ out,
                               __half* __restrict__ out_h) {
    __shared__ float buf[H];
    __shared__ float red[8];
    int t = blockIdx.x, tid = threadIdx.x;
    float ss = 0.f;
    for (int d = tid; d < H; d += 256) {
        float v = a[(size_t)t * H + d] + bb[(size_t)t * H + d];
        buf[d] = v;
        ss += v * v;
    }
    for (int o = 16; o; o >>= 1) ss += __shfl_xor_sync(~0u, ss, o);
    if ((tid & 31) == 0) red[tid >> 5] = ss;
    __syncthreads();
    if (tid < 8) {
        float x = red[tid];
        for (int o = 4; o; o >>= 1) x += __shfl_xor_sync(0xffu, x, o);
        if (tid == 0) red[0] = x;
    }
    __syncthreads();
    float inv = rsqrtf(red[0] / (float)H + 1.1920929e-7f);
    for (int d = tid; d < H; d += 256) {
        float v = buf[d] * inv * w[d];
        out[(size_t)t * H + d] = v;
        if (out_h) out_h[(size_t)t * H + d] = __float2half_rn(v);
    }
}

// ---------------- MoE combine (slots) + residual + RMSNorm -----------------
__global__ void moe_combine_norm(const float* __restrict__ w, float* __restrict__ out) {
    __shared__ float buf[H];
    __shared__ float red[8];
    int t = blockIdx.x, tid = threadIdx.x;
    int s0 = g_slot[t * 2], s1 = g_slot[t * 2 + 1];
    float w0 = g_slotw[t * 2], w1v = g_slotw[t * 2 + 1];
    float ss = 0.f;
    for (int d = tid; d < H; d += 256) {
        float v = g_x1[(size_t)t * H + d]
                + w0 * g_ybuf[(size_t)s0 * H + d]
                + w1v * g_ybuf[(size_t)s1 * H + d];
        buf[d] = v;
        ss += v * v;
    }
    for (int o = 16; o; o >>= 1) ss += __shfl_xor_sync(~0u, ss, o);
    if ((tid & 31) == 0) red[tid >> 5] = ss;
    __syncthreads();
    if (tid < 8) {
        float x = red[tid];
        for (int o = 4; o; o >>= 1) x += __shfl_xor_sync(0xffu, x, o);
        if (tid == 0) red[0] = x;
    }
    __syncthreads();
    float inv = rsqrtf(red[0] / (float)H + 1.1920929e-7f);
    for (int d = tid; d < H; d += 256)
        out[(size_t)t * H + d] = buf[d] * inv * w[d];
}

// ---------------- router -----------------------------------------------------
__global__ void router_kernel(const float* __restrict__ gate_w) {
    int warp = threadIdx.x >> 5, lane = threadIdx.x & 31;
    int t = blockIdx.x * 8 + warp;
    float acc[E];
#pragma unroll
    for (int e = 0; e < E; e++) acc[e] = 0.f;
    const float* xr = g_x1 + (size_t)t * H;
    for (int d = lane; d < H; d += 32) {
        float xv = xr[d];
        const float* g = gate_w + (size_t)d * E;
#pragma unroll
        for (int e = 0; e < E; e++) acc[e] += xv * g[e];
    }
#pragma unroll
    for (int e = 0; e < E; e++)
        for (int o = 16; o; o >>= 1) acc[e] += __shfl_xor_sync(~0u, acc[e], o);
    if (lane == 0) {
        float mx = acc[0];
#pragma unroll
        for (int e = 1; e < E; e++) mx = fmaxf(mx, acc[e]);
        float p[E]; float sum = 0.f;
#pragma unroll
        for (int e = 0; e < E; e++) { p[e] = expf(acc[e] - mx); sum += p[e]; }
        float inv = 1.f / sum;
#pragma unroll
        for (int e = 0; e < E; e++) p[e] *= inv;
        int i1 = 0;
#pragma unroll
        for (int e = 1; e < E; e++) if (p[e] > p[i1]) i1 = e;
        int i2 = -1;
#pragma unroll
        for (int e = 0; e < E; e++) {
            if (e == i1) continue;
            if (i2 < 0 || p[e] > p[i2]) i2 = e;
        }
        float s2 = p[i1] + p[i2];
        float w1n = p[i1] / s2, w2n = p[i2] / s2;
        int pos = atomicAdd(&g_cnt[i1], 1);
        g_tok[i1 * T + pos] = t;
        g_slot[t * 2] = i1 * T + pos;
        g_slotw[t * 2] = w1n;
        pos = atomicAdd(&g_cnt[i2], 1);
        g_tok[i2 * T + pos] = t;
        g_slot[t * 2 + 1] = i2 * T + pos;
        g_slotw[t * 2 + 1] = w2n;
#pragma unroll
        for (int e = 0; e < E; e++) atomicAdd(&g_probsum[e], p[e]);
    }
}

__global__ void aux_kernel(float* out) {
    float a = 0.f;
    for (int e = 0; e < E; e++)
        a += ((float)g_cnt[e] / (float)T) * (g_probsum[e] / (float)T);
    out[0] = (float)E * a;
}

// ---------------------------------------------------------------------------
extern "C" void kernel_launch(void* const* d_in, const int* in_sizes, int n_in,
                              void* d_out, int out_size) {
    const float* x      = (const float*)d_in[0];
    const int*   mask   = (const int*)  d_in[1];
    const float* qkv_w  = (const float*)d_in[2];
    const float* out_w  = (const float*)d_in[3];
    const float* gate_w = (const float*)d_in[4];
    const float* w1     = (const float*)d_in[5];
    const float* w2     = (const float*)d_in[6];
    const float* n1     = (const float*)d_in[7];
    const float* n2     = (const float*)d_in[8];
    float* out = (float*)d_out;

    float *p_attn, *p_x1;
    __half *p_qkv, *p_xt, *p_ctx, *p_x1t, *p_hmid;
    __half *p_qkvwT, *p_outwT, *p_w1T, *p_w2T;
    cudaGetSymbolAddress((void**)&p_qkv,   g_qkv);
    cudaGetSymbolAddress((void**)&p_ctx,   g_ctx);
    cudaGetSymbolAddress((void**)&p_attn,  g_attn);
    cudaGetSymbolAddress((void**)&p_x1,    g_x1);
    cudaGetSymbolAddress((void**)&p_x1t,   g_x1t);
    cudaGetSymbolAddress((void**)&p_xt,    g_xt);
    cudaGetSymbolAddress((void**)&p_hmid,  g_hmid);
    cudaGetSymbolAddress((void**)&p_qkvwT, g_qkvwT);
    cudaGetSymbolAddress((void**)&p_outwT, g_outwT);
    cudaGetSymbolAddress((void**)&p_w1T,   g_w1T);
    cudaGetSymbolAddress((void**)&p_w2T,   g_w2T);

    static bool attr_set = false;
    if (!attr_set) {
        cudaFuncSetAttribute(flash6_kernel,
                             cudaFuncAttributeMaxDynamicSharedMemorySize, FLASH_SMEM);
        cudaFuncSetAttribute(gemm_f16<0>,
                             cudaFuncAttributeMaxDynamicSharedMemorySize, GEMM_SMEM);
        cudaFuncSetAttribute(gemm_f16<1>,
                             cudaFuncAttributeMaxDynamicSharedMemorySize, GEMM_SMEM);
        cudaFuncSetAttribute(gemm_f16<2>,
                             cudaFuncAttributeMaxDynamicSharedMemorySize, GEMM_SMEM);
        cudaFuncSetAttribute(gemm_f16<3>,
                             cudaFuncAttributeMaxDynamicSharedMemorySize, GEMM_SMEM);
        attr_set = true;
    }

    zero_small<<<1, 32>>>();

    half_copy<<<(T * H + 255) / 256, 256>>>(x, p_xt, T * H);
    transpose_half<<<dim3(H3 / 32, H / 32, 1), dim3(32, 8)>>>(qkv_w, p_qkvwT, H, H3);
    transpose_half<<<dim3(H / 32, H / 32, 1),  dim3(32, 8)>>>(out_w, p_outwT, H, H);
    transpose_half<<<dim3(F / 32, H / 32, E),  dim3(32, 8)>>>(w1, p_w1T, H, F);
    transpose_half<<<dim3(H / 32, F / 32, E),  dim3(32, 8)>>>(w2, p_w2T, F, H);

    // QKV projection (fp16 out)
    gemm_f16<3><<<dim3(H3 / BN, T / BM, 1), 256, GEMM_SMEM>>>(p_xt, p_qkvwT, p_qkv, T, H3, H);

    rope2_kernel<<<(T * NH * 32 + 255) / 256, 256>>>();
    vtrans_kernel<<<dim3(S / 32, HD / 32, B * NH), dim3(32, 8)>>>();

    flash6_kernel<<<dim3(S / 128, NH, B), 256, FLASH_SMEM>>>(mask);

    // out projection (fp32 out)
    gemm_f16<0><<<dim3(H / BN, T / BM, 1), 256, GEMM_SMEM>>>(p_ctx, p_outwT, p_attn, T, H, H);

    addnorm_kernel<<<T, 256>>>(x, p_attn, n1, p_x1, p_x1t);

    router_kernel<<<T / 8, 256>>>(gate_w);
    aux_kernel<<<1, 1>>>(out + (size_t)T * H);

    gemm_f16<1><<<dim3(F / BN, T / BM, E), 256, GEMM_SMEM>>>(p_x1t, p_w1T, nullptr, T, F, H);
    gemm_f16<2><<<dim3(H / BN, T / BM, E), 256, GEMM_SMEM>>>(p_hmid, p_w2T, nullptr, T, H, F);

    moe_combine_norm<<<T, 256>>>(n2, out);
}

// round 16
// speedup vs baseline: 1.0421x; 1.0211x over previous
#include <cuda_runtime.h>
#include <cuda_fp16.h>
#include <stdint.h>
#include <math.h>

#define B 4
#define S 2048
#define H 768
#define NH 12
#define HD 64
#define E 8
#define TOPK 2
#define F 3072
#define T (B*S)      /* 8192 tokens */
#define H3 (3*H)     /* 2304 */

// ---------------- scratch (device globals: no runtime allocation) ----------
__device__ __half g_qkv[(size_t)T*H3];
__device__ __half g_qTh[(size_t)T*H];
__device__ __half g_kTh[(size_t)T*H];
__device__ __half g_vTh[(size_t)T*H];
__device__ __half g_xt[(size_t)T*H];
__device__ __half g_ctx[(size_t)T*H];
__device__ float  g_attn[(size_t)T*H];
__device__ float  g_x1[(size_t)T*H];
__device__ __half g_x1t[(size_t)T*H];
__device__ __half g_hmid[(size_t)E*T*F];
__device__ float  g_ybuf[(size_t)E*T*H];
__device__ __half g_qkvwT[(size_t)H3*H];
__device__ __half g_outwT[(size_t)H*H];
__device__ __half g_w1T[(size_t)E*F*H];
__device__ __half g_w2T[(size_t)E*H*F];
__device__ int    g_cnt[E];
__device__ float  g_probsum[E];
__device__ int    g_tok[E*T];
__device__ int    g_slot[T*TOPK];
__device__ float  g_slotw[T*TOPK];

#define MMA_F16(d0,d1,d2,d3,a0,a1,a2,a3,b0,b1) \
    asm volatile("mma.sync.aligned.m16n8k16.row.col.f32.f16.f16.f32 " \
                 "{%0,%1,%2,%3},{%4,%5,%6,%7},{%8,%9},{%0,%1,%2,%3};" \
                 : "+f"(d0), "+f"(d1), "+f"(d2), "+f"(d3) \
                 : "r"(a0), "r"(a1), "r"(a2), "r"(a3), "r"(b0), "r"(b1))

__device__ __forceinline__ void cp_async16(void* smem_dst, const void* gsrc) {
    uint32_t saddr = (uint32_t)__cvta_generic_to_shared(smem_dst);
    asm volatile("cp.async.ca.shared.global [%0], [%1], 16;" :: "r"(saddr), "l"(gsrc));
}
#define CP_COMMIT asm volatile("cp.async.commit_group;")
#define CP_WAIT0  asm volatile("cp.async.wait_group 0;")
#define CP_WAIT1  asm volatile("cp.async.wait_group 1;")

__device__ __forceinline__ uint32_t h2_u32(float a, float b) {
    __half2 h = __floats2half2_rn(a, b);
    return *(uint32_t*)&h;
}

// ---------------- producers -------------------------------------------------
// half copy + zero-init of router counters (block 0)
__global__ void half_copy_init(const float* __restrict__ src, __half* __restrict__ dst, int n) {
    int i = blockIdx.x * blockDim.x + threadIdx.x;
    if (i < n) dst[i] = __float2half_rn(src[i]);
    if (blockIdx.x == 0 && threadIdx.x < E) {
        g_cnt[threadIdx.x] = 0;
        g_probsum[threadIdx.x] = 0.f;
    }
}

__global__ void transpose_half(const float* __restrict__ src, __half* __restrict__ dst,
                               int R, int C) {
    __shared__ float tile[32][33];
    int e = blockIdx.z;
    src += (size_t)e * R * C;
    dst += (size_t)e * R * C;
    int c0 = blockIdx.x * 32, r0 = blockIdx.y * 32;
    int tx = threadIdx.x, ty0 = threadIdx.y;
    for (int ty = ty0; ty < 32; ty += 8)
        tile[ty][tx] = src[(size_t)(r0 + ty) * C + c0 + tx];
    __syncthreads();
    for (int ty = ty0; ty < 32; ty += 8)
        dst[(size_t)(c0 + ty) * R + r0 + tx] = __float2half_rn(tile[tx][ty]);
}

__global__ void vtrans_kernel() {
    __shared__ __half tile[32][34];
    int bh = blockIdx.z;
    int b = bh / NH, h = bh % NH;
    int s0 = blockIdx.x * 32, d0 = blockIdx.y * 32;
    int tx = threadIdx.x, ty0 = threadIdx.y;
    const __half* src = g_qkv + (size_t)b * S * H3 + (size_t)h * 192 + 128;
    for (int ty = ty0; ty < 32; ty += 8)
        tile[ty][tx] = src[(size_t)(s0 + ty) * H3 + d0 + tx];
    __syncthreads();
    __half* dst = g_vTh + ((size_t)bh * HD) * S;
    for (int ty = ty0; ty < 32; ty += 8)
        dst[(size_t)(d0 + ty) * S + s0 + tx] = tile[tx][ty];
}

// ---------------- fp16 tensor-core GEMM, 3-stage cp.async, 128x128 ---------
#define BM 128
#define BN 128
#define BK 32
#define ASTR 40
#define GEMM_SMEM (3 * (BM*ASTR + BN*ASTR) * 2)   /* 61440 B */

template<int MODE>
__global__ void __launch_bounds__(256) gemm_f16(
    const __half* __restrict__ A, const __half* __restrict__ WT,
    void* __restrict__ CoutV, int M, int N, int K)
{
    extern __shared__ __half hsm[];
    __half* AsP = hsm;
    __half* BsP = hsm + 3 * BM * ASTR;
    __shared__ int rt_s[BM];

    int e = blockIdx.z;
    int c = M;
    int r0 = blockIdx.y * BM;
    if (MODE == 1 || MODE == 2) {
        c = g_cnt[e];
        if (r0 >= c) return;
    }
    int col0 = blockIdx.x * BN;
    int tid = threadIdx.x;

    const __half* Ab = A;
    const __half* Wb = WT;
    if (MODE == 1) { Wb = WT + (size_t)e * N * K; }
    if (MODE == 2) { Ab = A + (size_t)e * T * K; Wb = WT + (size_t)e * N * K; }

    if (MODE == 1) {
        if (tid < BM) {
            int r = r0 + tid;
            rt_s[tid] = (r < c) ? g_tok[e * T + r] : 0;
        }
        __syncthreads();
    }

    int lane = tid & 31, warp = tid >> 5;
    int wm = warp >> 2, wn = warp & 3;
    int g = lane >> 2, cq = lane & 3;

    auto issueA = [&](int stage, int k0) {
        __half* dst = AsP + stage * BM * ASTR;
#pragma unroll
        for (int i = 0; i < 2; i++) {
            int lin = tid + i * 256;
            int r = lin >> 2, ch = lin & 3;
            const __half* src;
            if (MODE == 1) src = Ab + (size_t)rt_s[r] * K + k0 + ch * 8;
            else           src = Ab + (size_t)(r0 + r) * K + k0 + ch * 8;
            cp_async16(dst + r * ASTR + ch * 8, src);
        }
    };
    auto issueB = [&](int stage, int k0) {
        __half* dst = BsP + stage * BN * ASTR;
#pragma unroll
        for (int i = 0; i < 2; i++) {
            int lin = tid + i * 256;
            int r = lin >> 2, ch = lin & 3;
            cp_async16(dst + r * ASTR + ch * 8, Wb + (size_t)(col0 + r) * K + k0 + ch * 8);
        }
    };

    float acc[4][4][4];
#pragma unroll
    for (int i = 0; i < 4; i++)
#pragma unroll
        for (int j = 0; j < 4; j++)
#pragma unroll
            for (int k = 0; k < 4; k++) acc[i][j][k] = 0.f;

    int nIter = K / BK;
    issueA(0, 0); issueB(0, 0); CP_COMMIT;
    issueA(1, BK); issueB(1, BK); CP_COMMIT;
    int cur = 0;

    for (int it = 0; it < nIter; it++) {
        if (it < nIter - 1) { CP_WAIT1; } else { CP_WAIT0; }
        __syncthreads();
        if (it + 2 < nIter) {
            int st = (it + 2) % 3;
            issueA(st, (it + 2) * BK);
            issueB(st, (it + 2) * BK);
            CP_COMMIT;
        }
        const __half* Ac = AsP + cur * BM * ASTR;
        const __half* Bc = BsP + cur * BN * ASTR;
#pragma unroll
        for (int kk = 0; kk < BK; kk += 16) {
            uint32_t a[4][4], b[4][2];
#pragma unroll
            for (int mt = 0; mt < 4; mt++) {
                int m0 = wm * 64 + mt * 16;
                a[mt][0] = *(const uint32_t*)(Ac + (m0 + g    ) * ASTR + kk + 2 * cq);
                a[mt][1] = *(const uint32_t*)(Ac + (m0 + g + 8) * ASTR + kk + 2 * cq);
                a[mt][2] = *(const uint32_t*)(Ac + (m0 + g    ) * ASTR + kk + 2 * cq + 8);
                a[mt][3] = *(const uint32_t*)(Ac + (m0 + g + 8) * ASTR + kk + 2 * cq + 8);
            }
#pragma unroll
            for (int nt = 0; nt < 4; nt++) {
                int n0 = wn * 32 + nt * 8;
                b[nt][0] = *(const uint32_t*)(Bc + (n0 + g) * ASTR + kk + 2 * cq);
                b[nt][1] = *(const uint32_t*)(Bc + (n0 + g) * ASTR + kk + 2 * cq + 8);
            }
#pragma unroll
            for (int mt = 0; mt < 4; mt++)
#pragma unroll
                for (int nt = 0; nt < 4; nt++) {
                    MMA_F16(acc[mt][nt][0], acc[mt][nt][1], acc[mt][nt][2], acc[mt][nt][3],
                            a[mt][0], a[mt][1], a[mt][2], a[mt][3],
                            b[nt][0], b[nt][1]);
                }
        }
        cur = (cur + 1) % 3;
    }

    float* Cf = (float*)CoutV;
    __half* Ch = (__half*)CoutV;
#pragma unroll
    for (int mt = 0; mt < 4; mt++) {
#pragma unroll
        for (int nt = 0; nt < 4; nt++) {
#pragma unroll
            for (int hf = 0; hf < 2; hf++) {
                int lrow = wm * 64 + mt * 16 + g + hf * 8;
                int col = col0 + wn * 32 + nt * 8 + cq * 2;
                float v0 = acc[mt][nt][hf * 2 + 0];
                float v1 = acc[mt][nt][hf * 2 + 1];
                if (MODE == 0) {
                    Cf[(size_t)(r0 + lrow) * N + col]     = v0;
                    Cf[(size_t)(r0 + lrow) * N + col + 1] = v1;
                } else if (MODE == 3) {
                    Ch[(size_t)(r0 + lrow) * N + col]     = __float2half_rn(v0);
                    Ch[(size_t)(r0 + lrow) * N + col + 1] = __float2half_rn(v1);
                } else if (MODE == 1) {
                    int r = r0 + lrow;
                    if (r < c) {
                        float g0 = 0.5f * v0 * (1.f + erff(v0 * 0.70710678118f));
                        float g1 = 0.5f * v1 * (1.f + erff(v1 * 0.70710678118f));
                        g_hmid[((size_t)e * T + r) * F + col]     = __float2half_rn(g0);
                        g_hmid[((size_t)e * T + r) * F + col + 1] = __float2half_rn(g1);
                    }
                } else {
                    int r = r0 + lrow;
                    if (r < c) {
                        g_ybuf[((size_t)e * T + r) * H + col]     = v0;
                        g_ybuf[((size_t)e * T + r) * H + col + 1] = v1;
                    }
                }
            }
        }
    }
}

// ---------------- RoPE (reads fp16 qkv) -> fp16 Q (scaled), K --------------
__global__ void rope2_kernel() {
    int idx = blockIdx.x * blockDim.x + threadIdx.x;
    if (idx >= T * NH * 32) return;
    int i = idx & 31;
    int h = (idx >> 5) % NH;
    int t = idx / (32 * NH);
    int b = t / S, s = t % S;
    float invf = expf(-(float)i * (9.210340371976184f / 32.f));
    float th = (float)s * invf;
    float c = cosf(th), sn = sinf(th);
    const __half* p = g_qkv + (size_t)t * H3 + h * 192;
    size_t dbase = ((size_t)(b * NH + h) * S + s) * HD;
    float q1 = __half2float(p[i]), q2 = __half2float(p[i + 32]);
    g_qTh[dbase + i]      = __float2half_rn((q1 * c - q2 * sn) * 0.125f);
    g_qTh[dbase + i + 32] = __float2half_rn((q2 * c + q1 * sn) * 0.125f);
    float k1 = __half2float(p[64 + i]), k2 = __half2float(p[64 + i + 32]);
    g_kTh[dbase + i]      = __float2half_rn(k1 * c - k2 * sn);
    g_kTh[dbase + i + 32] = __float2half_rn(k2 * c + k1 * sn);
}

// ---------------- flash attention v6: full fp16 MMA, P in registers --------
#define KSH 72
#define VSH 72
#define FLASH_SMEM ((2*64*KSH + 2*64*VSH) * 2 + 2 * 64 * 4)

__global__ void __launch_bounds__(256) flash6_kernel(const int* __restrict__ mask) {
    extern __shared__ __half hfs[];
    __half* Kb = hfs;
    __half* Vb = Kb + 2 * 64 * KSH;
    int*    Mb = (int*)(Vb + 2 * 64 * VSH);

    int tid = threadIdx.x;
    int lane = tid & 31, warp = tid >> 5;
    int g = lane >> 2, cq = lane & 3;
    int q0 = blockIdx.x * 128, h = blockIdx.y, b = blockIdx.z;
    size_t bh = (size_t)(b * NH + h) * S;

    uint32_t qf[4][4];
    {
        const __half* qr0 = g_qTh + (bh + q0 + warp * 16 + g) * HD;
        const __half* qr1 = qr0 + 8 * HD;
#pragma unroll
        for (int cc = 0; cc < 4; cc++) {
            qf[cc][0] = *(const uint32_t*)(qr0 + cc * 16 + 2 * cq);
            qf[cc][1] = *(const uint32_t*)(qr1 + cc * 16 + 2 * cq);
            qf[cc][2] = *(const uint32_t*)(qr0 + cc * 16 + 2 * cq + 8);
            qf[cc][3] = *(const uint32_t*)(qr1 + cc * 16 + 2 * cq + 8);
        }
    }

    auto issueKV = [&](int buf, int k0) {
#pragma unroll
        for (int i = 0; i < 4; i++) {
            int lin = tid + i * 256;
            int row = lin >> 3, ch = lin & 7;
            if (row < 64) {
                const __half* src = g_kTh + (bh + k0 + row) * HD + ch * 8;
                cp_async16(Kb + buf * 64 * KSH + row * KSH + ch * 8, src);
            } else {
                int d = row - 64;
                const __half* src = g_vTh + ((size_t)(b * NH + h) * HD + d) * S + k0 + ch * 8;
                cp_async16(Vb + buf * 64 * VSH + d * VSH + ch * 8, src);
            }
        }
        if (tid < 16)
            cp_async16(Mb + buf * 64 + tid * 4, mask + b * S + k0 + tid * 4);
    };

    float acc_o[8][4];
#pragma unroll
    for (int nt = 0; nt < 8; nt++)
#pragma unroll
        for (int j = 0; j < 4; j++) acc_o[nt][j] = 0.f;
    float m0r = -1e30f, m1r = -1e30f, l0 = 0.f, l1 = 0.f;

    uint32_t fullm = 0xffffffffu;

    issueKV(0, 0);
    CP_COMMIT;
    int cur = 0;

    for (int k0 = 0; k0 < S; k0 += 64) {
        CP_WAIT0;
        __syncthreads();
        if (k0 + 64 < S) {
            issueKV(cur ^ 1, k0 + 64);
            CP_COMMIT;
        }
        const __half* Kc = Kb + cur * 64 * KSH;
        const __half* Vc = Vb + cur * 64 * VSH;
        const int*    Mc = Mb + cur * 64;

        float sacc[8][4];
#pragma unroll
        for (int nt = 0; nt < 8; nt++)
#pragma unroll
            for (int j = 0; j < 4; j++) sacc[nt][j] = 0.f;
#pragma unroll
        for (int cc = 0; cc < 4; cc++) {
            int kk = cc * 16;
#pragma unroll
            for (int nt = 0; nt < 8; nt++) {
                uint32_t b0 = *(const uint32_t*)(Kc + (nt * 8 + g) * KSH + kk + 2 * cq);
                uint32_t b1 = *(const uint32_t*)(Kc + (nt * 8 + g) * KSH + kk + 2 * cq + 8);
                MMA_F16(sacc[nt][0], sacc[nt][1], sacc[nt][2], sacc[nt][3],
                        qf[cc][0], qf[cc][1], qf[cc][2], qf[cc][3], b0, b1);
            }
        }

        float mx0 = -1e30f, mx1 = -1e30f;
#pragma unroll
        for (int nt = 0; nt < 8; nt++) {
            float mk0 = (Mc[nt * 8 + cq * 2]     == 0) ? -1e30f : 0.f;
            float mk1 = (Mc[nt * 8 + cq * 2 + 1] == 0) ? -1e30f : 0.f;
            sacc[nt][0] += mk0; sacc[nt][1] += mk1;
            sacc[nt][2] += mk0; sacc[nt][3] += mk1;
            mx0 = fmaxf(mx0, fmaxf(sacc[nt][0], sacc[nt][1]));
            mx1 = fmaxf(mx1, fmaxf(sacc[nt][2], sacc[nt][3]));
        }
        mx0 = fmaxf(mx0, __shfl_xor_sync(fullm, mx0, 1));
        mx0 = fmaxf(mx0, __shfl_xor_sync(fullm, mx0, 2));
        mx1 = fmaxf(mx1, __shfl_xor_sync(fullm, mx1, 1));
        mx1 = fmaxf(mx1, __shfl_xor_sync(fullm, mx1, 2));
        float newm0 = fmaxf(m0r, mx0), newm1 = fmaxf(m1r, mx1);
        float sc0 = __expf(m0r - newm0), sc1 = __expf(m1r - newm1);
        m0r = newm0; m1r = newm1;
        float ps0 = 0.f, ps1 = 0.f;
#pragma unroll
        for (int nt = 0; nt < 8; nt++) {
            sacc[nt][0] = __expf(sacc[nt][0] - newm0);
            sacc[nt][1] = __expf(sacc[nt][1] - newm0);
            sacc[nt][2] = __expf(sacc[nt][2] - newm1);
            sacc[nt][3] = __expf(sacc[nt][3] - newm1);
            ps0 += sacc[nt][0] + sacc[nt][1];
            ps1 += sacc[nt][2] + sacc[nt][3];
            acc_o[nt][0] *= sc0; acc_o[nt][1] *= sc0;
            acc_o[nt][2] *= sc1; acc_o[nt][3] *= sc1;
        }
        ps0 += __shfl_xor_sync(fullm, ps0, 1); ps0 += __shfl_xor_sync(fullm, ps0, 2);
        ps1 += __shfl_xor_sync(fullm, ps1, 1); ps1 += __shfl_xor_sync(fullm, ps1, 2);
        l0 = l0 * sc0 + ps0;
        l1 = l1 * sc1 + ps1;

#pragma unroll
        for (int kt = 0; kt < 4; kt++) {
            uint32_t a0 = h2_u32(sacc[2*kt][0],   sacc[2*kt][1]);
            uint32_t a1 = h2_u32(sacc[2*kt][2],   sacc[2*kt][3]);
            uint32_t a2 = h2_u32(sacc[2*kt+1][0], sacc[2*kt+1][1]);
            uint32_t a3 = h2_u32(sacc[2*kt+1][2], sacc[2*kt+1][3]);
            int kk = kt * 16;
#pragma unroll
            for (int nt = 0; nt < 8; nt++) {
                uint32_t b0 = *(const uint32_t*)(Vc + (nt * 8 + g) * VSH + kk + 2 * cq);
                uint32_t b1 = *(const uint32_t*)(Vc + (nt * 8 + g) * VSH + kk + 2 * cq + 8);
                MMA_F16(acc_o[nt][0], acc_o[nt][1], acc_o[nt][2], acc_o[nt][3],
                        a0, a1, a2, a3, b0, b1);
            }
        }
        cur ^= 1;
    }

    float inv0 = 1.f / l0, inv1 = 1.f / l1;
    size_t row0 = (size_t)(b * S + q0 + warp * 16 + g) * H + h * HD;
    size_t row1 = row0 + (size_t)8 * H;
#pragma unroll
    for (int nt = 0; nt < 8; nt++) {
        int col = nt * 8 + cq * 2;
        g_ctx[row0 + col]     = __float2half_rn(acc_o[nt][0] * inv0);
        g_ctx[row0 + col + 1] = __float2half_rn(acc_o[nt][1] * inv0);
        g_ctx[row1 + col]     = __float2half_rn(acc_o[nt][2] * inv1);
        g_ctx[row1 + col + 1] = __float2half_rn(acc_o[nt][3] * inv1);
    }
}

// ---------------- fused: residual add + RMSNorm + router -------------------
// one block per token, 256 threads. Router logits computed from smem buf
// (warp e owns expert e; identical summation order to prior router_kernel).
__global__ void addnorm_router(const float* __restrict__ a, const float* __restrict__ bb,
                               const float* __restrict__ w,
                               const float* __restrict__ gate_w,
                               float* __restrict__ out, __half* __restrict__ out_h) {
    __shared__ float buf[H];
    __shared__ float red[8];
    __shared__ float logits[E];
    int t = blockIdx.x, tid = threadIdx.x;
    int lane = tid & 31, warp = tid >> 5;
    float ss = 0.f;
    for (int d = tid; d < H; d += 256) {
        float v = a[(size_t)t * H + d] + bb[(size_t)t * H + d];
        buf[d] = v;
        ss += v * v;
    }
    for (int o = 16; o; o >>= 1) ss += __shfl_xor_sync(~0u, ss, o);
    if (lane == 0) red[warp] = ss;
    __syncthreads();
    if (tid < 8) {
        float x = red[tid];
        for (int o = 4; o; o >>= 1) x += __shfl_xor_sync(0xffu, x, o);
        if (tid == 0) red[0] = x;
    }
    __syncthreads();
    float inv = rsqrtf(red[0] / (float)H + 1.1920929e-7f);
    for (int d = tid; d < H; d += 256) {
        float v = buf[d] * inv * w[d];
        out[(size_t)t * H + d] = v;
        out_h[(size_t)t * H + d] = __float2half_rn(v);
        buf[d] = v;   // reuse buf as normalized row for router
    }
    __syncthreads();
    // router: warp e computes logit for expert e
    {
        int e = warp;
        float acc = 0.f;
        for (int d = lane; d < H; d += 32)
            acc += buf[d] * gate_w[(size_t)d * E + e];
        for (int o = 16; o; o >>= 1) acc += __shfl_xor_sync(~0u, acc, o);
        if (lane == 0) logits[e] = acc;
    }
    __syncthreads();
    if (tid == 0) {
        float mx = logits[0];
#pragma unroll
        for (int e = 1; e < E; e++) mx = fmaxf(mx, logits[e]);
        float p[E]; float sum = 0.f;
#pragma unroll
        for (int e = 0; e < E; e++) { p[e] = expf(logits[e] - mx); sum += p[e]; }
        float pinv = 1.f / sum;
#pragma unroll
        for (int e = 0; e < E; e++) p[e] *= pinv;
        int i1 = 0;
#pragma unroll
        for (int e = 1; e < E; e++) if (p[e] > p[i1]) i1 = e;
        int i2 = -1;
#pragma unroll
        for (int e = 0; e < E; e++) {
            if (e == i1) continue;
            if (i2 < 0 || p[e] > p[i2]) i2 = e;
        }
        float s2 = p[i1] + p[i2];
        float w1n = p[i1] / s2, w2n = p[i2] / s2;
        int pos = atomicAdd(&g_cnt[i1], 1);
        g_tok[i1 * T + pos] = t;
        g_slot[t * 2] = i1 * T + pos;
        g_slotw[t * 2] = w1n;
        pos = atomicAdd(&g_cnt[i2], 1);
        g_tok[i2 * T + pos] = t;
        g_slot[t * 2 + 1] = i2 * T + pos;
        g_slotw[t * 2 + 1] = w2n;
#pragma unroll
        for (int e = 0; e < E; e++) atomicAdd(&g_probsum[e], p[e]);
    }
}

// ---------------- MoE combine + residual + RMSNorm (+ aux in block 0) ------
__global__ void moe_combine_norm(const float* __restrict__ w, float* __restrict__ out,
                                 float* __restrict__ aux_out) {
    __shared__ float buf[H];
    __shared__ float red[8];
    int t = blockIdx.x, tid = threadIdx.x;
    if (t == 0 && tid == 0) {
        float a = 0.f;
        for (int e = 0; e < E; e++)
            a += ((float)g_cnt[e] / (float)T) * (g_probsum[e] / (float)T);
        aux_out[0] = (float)E * a;
    }
    int s0 = g_slot[t * 2], s1 = g_slot[t * 2 + 1];
    float w0 = g_slotw[t * 2], w1v = g_slotw[t * 2 + 1];
    float ss = 0.f;
    for (int d = tid; d < H; d += 256) {
        float v = g_x1[(size_t)t * H + d]
                + w0 * g_ybuf[(size_t)s0 * H + d]
                + w1v * g_ybuf[(size_t)s1 * H + d];
        buf[d] = v;
        ss += v * v;
    }
    for (int o = 16; o; o >>= 1) ss += __shfl_xor_sync(~0u, ss, o);
    if ((tid & 31) == 0) red[tid >> 5] = ss;
    __syncthreads();
    if (tid < 8) {
        float x = red[tid];
        for (int o = 4; o; o >>= 1) x += __shfl_xor_sync(0xffu, x, o);
        if (tid == 0) red[0] = x;
    }
    __syncthreads();
    float inv = rsqrtf(red[0] / (float)H + 1.1920929e-7f);
    for (int d = tid; d < H; d += 256)
        out[(size_t)t * H + d] = buf[d] * inv * w[d];
}

// ---------------------------------------------------------------------------
extern "C" void kernel_launch(void* const* d_in, const int* in_sizes, int n_in,
                              void* d_out, int out_size) {
    const float* x      = (const float*)d_in[0];
    const int*   mask   = (const int*)  d_in[1];
    const float* qkv_w  = (const float*)d_in[2];
    const float* out_w  = (const float*)d_in[3];
    const float* gate_w = (const float*)d_in[4];
    const float* w1     = (const float*)d_in[5];
    const float* w2     = (const float*)d_in[6];
    const float* n1     = (const float*)d_in[7];
    const float* n2     = (const float*)d_in[8];
    float* out = (float*)d_out;

    float *p_attn, *p_x1;
    __half *p_qkv, *p_xt, *p_ctx, *p_x1t, *p_hmid;
    __half *p_qkvwT, *p_outwT, *p_w1T, *p_w2T;
    cudaGetSymbolAddress((void**)&p_qkv,   g_qkv);
    cudaGetSymbolAddress((void**)&p_ctx,   g_ctx);
    cudaGetSymbolAddress((void**)&p_attn,  g_attn);
    cudaGetSymbolAddress((void**)&p_x1,    g_x1);
    cudaGetSymbolAddress((void**)&p_x1t,   g_x1t);
    cudaGetSymbolAddress((void**)&p_xt,    g_xt);
    cudaGetSymbolAddress((void**)&p_hmid,  g_hmid);
    cudaGetSymbolAddress((void**)&p_qkvwT, g_qkvwT);
    cudaGetSymbolAddress((void**)&p_outwT, g_outwT);
    cudaGetSymbolAddress((void**)&p_w1T,   g_w1T);
    cudaGetSymbolAddress((void**)&p_w2T,   g_w2T);

    static bool attr_set = false;
    if (!attr_set) {
        cudaFuncSetAttribute(flash6_kernel,
                             cudaFuncAttributeMaxDynamicSharedMemorySize, FLASH_SMEM);
        cudaFuncSetAttribute(gemm_f16<0>,
                             cudaFuncAttributeMaxDynamicSharedMemorySize, GEMM_SMEM);
        cudaFuncSetAttribute(gemm_f16<1>,
                             cudaFuncAttributeMaxDynamicSharedMemorySize, GEMM_SMEM);
        cudaFuncSetAttribute(gemm_f16<2>,
                             cudaFuncAttributeMaxDynamicSharedMemorySize, GEMM_SMEM);
        cudaFuncSetAttribute(gemm_f16<3>,
                             cudaFuncAttributeMaxDynamicSharedMemorySize, GEMM_SMEM);
        attr_set = true;
    }

    // #1: fp16 copy of x (+ zero router counters)
    half_copy_init<<<(T * H + 255) / 256, 256>>>(x, p_xt, T * H);
    // #2: qkv weight transpose
    transpose_half<<<dim3(H3 / 32, H / 32, 1), dim3(32, 8)>>>(qkv_w, p_qkvwT, H, H3);
    // #3: QKV projection (fp16 out)
    gemm_f16<3><<<dim3(H3 / BN, T / BM, 1), 256, GEMM_SMEM>>>(p_xt, p_qkvwT, p_qkv, T, H3, H);
    // #4: rope
    rope2_kernel<<<(T * NH * 32 + 255) / 256, 256>>>();
    // #5: v transpose
    vtrans_kernel<<<dim3(S / 32, HD / 32, B * NH), dim3(32, 8)>>>();
    // #6: flash  (ncu -s 5 -c 1 profiles this one)
    flash6_kernel<<<dim3(S / 128, NH, B), 256, FLASH_SMEM>>>(mask);

    // remaining weight transposes (not needed until now / later)
    transpose_half<<<dim3(H / 32, H / 32, 1),  dim3(32, 8)>>>(out_w, p_outwT, H, H);
    gemm_f16<0><<<dim3(H / BN, T / BM, 1), 256, GEMM_SMEM>>>(p_ctx, p_outwT, p_attn, T, H, H);

    addnorm_router<<<T, 256>>>(x, p_attn, n1, gate_w, p_x1, p_x1t);

    transpose_half<<<dim3(F / 32, H / 32, E),  dim3(32, 8)>>>(w1, p_w1T, H, F);
    gemm_f16<1><<<dim3(F / BN, T / BM, E), 256, GEMM_SMEM>>>(p_x1t, p_w1T, nullptr, T, F, H);

    transpose_half<<<dim3(H / 32, F / 32, E),  dim3(32, 8)>>>(w2, p_w2T, F, H);
    gemm_f16<2><<<dim3(H / BN, T / BM, E), 256, GEMM_SMEM>>>(p_hmid, p_w2T, nullptr, T, H, F);

    moe_combine_norm<<<T, 256>>>(n2, out, out + (size_t)T * H);
}

// round 17
// speedup vs baseline: 1.1750x; 1.1275x over previous
#include <cuda_runtime.h>
#include <cuda_fp16.h>
#include <stdint.h>
#include <math.h>

#define B 4
#define S 2048
#define H 768
#define NH 12
#define HD 64
#define E 8
#define TOPK 2
#define F 3072
#define T (B*S)      /* 8192 tokens */
#define H3 (3*H)     /* 2304 */

// ---------------- scratch (device globals: no runtime allocation) ----------
__device__ __half g_qkv[(size_t)T*H3];
__device__ __half g_qTh[(size_t)T*H];
__device__ __half g_kTh[(size_t)T*H];
__device__ __half g_vTh[(size_t)T*H];
__device__ __half g_xt[(size_t)T*H];
__device__ __half g_ctx[(size_t)T*H];
__device__ float  g_attn[(size_t)T*H];
__device__ float  g_x1[(size_t)T*H];
__device__ __half g_x1t[(size_t)T*H];
__device__ __half g_hmid[(size_t)E*T*F];
__device__ float  g_ybuf[(size_t)E*T*H];
__device__ __half g_qkvwT[(size_t)H3*H];
__device__ __half g_outwT[(size_t)H*H];
__device__ __half g_w1T[(size_t)E*F*H];
__device__ __half g_w2T[(size_t)E*H*F];
__device__ int    g_cnt[E];
__device__ float  g_probsum[E];
__device__ int    g_tok[E*T];
__device__ int    g_slot[T*TOPK];
__device__ float  g_slotw[T*TOPK];

#define MMA_F16(d0,d1,d2,d3,a0,a1,a2,a3,b0,b1) \
    asm volatile("mma.sync.aligned.m16n8k16.row.col.f32.f16.f16.f32 " \
                 "{%0,%1,%2,%3},{%4,%5,%6,%7},{%8,%9},{%0,%1,%2,%3};" \
                 : "+f"(d0), "+f"(d1), "+f"(d2), "+f"(d3) \
                 : "r"(a0), "r"(a1), "r"(a2), "r"(a3), "r"(b0), "r"(b1))

__device__ __forceinline__ void ldsm_x4(uint32_t& r0, uint32_t& r1, uint32_t& r2,
                                        uint32_t& r3, uint32_t saddr) {
    asm volatile("ldmatrix.sync.aligned.m8n8.x4.shared.b16 {%0,%1,%2,%3}, [%4];"
                 : "=r"(r0), "=r"(r1), "=r"(r2), "=r"(r3) : "r"(saddr));
}

__device__ __forceinline__ void cp_async16(void* smem_dst, const void* gsrc) {
    uint32_t saddr = (uint32_t)__cvta_generic_to_shared(smem_dst);
    asm volatile("cp.async.ca.shared.global [%0], [%1], 16;" :: "r"(saddr), "l"(gsrc));
}
#define CP_COMMIT asm volatile("cp.async.commit_group;")
#define CP_WAIT0  asm volatile("cp.async.wait_group 0;")
#define CP_WAIT1  asm volatile("cp.async.wait_group 1;")

__device__ __forceinline__ uint32_t h2_u32(float a, float b) {
    __half2 h = __floats2half2_rn(a, b);
    return *(uint32_t*)&h;
}
__device__ __forceinline__ uint32_t smem_u32(const void* p) {
    return (uint32_t)__cvta_generic_to_shared(p);
}

// ---------------- producers -------------------------------------------------
__global__ void half_copy_init(const float* __restrict__ src, __half* __restrict__ dst, int n) {
    int i = blockIdx.x * blockDim.x + threadIdx.x;
    if (i < n) dst[i] = __float2half_rn(src[i]);
    if (blockIdx.x == 0 && threadIdx.x < E) {
        g_cnt[threadIdx.x] = 0;
        g_probsum[threadIdx.x] = 0.f;
    }
}

__global__ void transpose_half(const float* __restrict__ src, __half* __restrict__ dst,
                               int R, int C) {
    __shared__ float tile[32][33];
    int e = blockIdx.z;
    src += (size_t)e * R * C;
    dst += (size_t)e * R * C;
    int c0 = blockIdx.x * 32, r0 = blockIdx.y * 32;
    int tx = threadIdx.x, ty0 = threadIdx.y;
    for (int ty = ty0; ty < 32; ty += 8)
        tile[ty][tx] = src[(size_t)(r0 + ty) * C + c0 + tx];
    __syncthreads();
    for (int ty = ty0; ty < 32; ty += 8)
        dst[(size_t)(c0 + ty) * R + r0 + tx] = __float2half_rn(tile[tx][ty]);
}

// fused RoPE (q,k) + V-transpose. grid (S/32, B*NH), block (32,8).
__global__ void ropev_kernel() {
    __shared__ __half vs[32][66];
    int bh = blockIdx.y;
    int b = bh / NH, h = bh % NH;
    int s0 = blockIdx.x * 32;
    int tx = threadIdx.x, ty = threadIdx.y;
    const __half* base = g_qkv + (size_t)b * S * H3 + (size_t)h * 192;
    float invf = expf(-(float)tx * (9.210340371976184f / 32.f));
    for (int r = ty; r < 32; r += 8) {
        int s = s0 + r;
        const __half* p = base + (size_t)s * H3;
        float th = (float)s * invf;
        float c = cosf(th), sn = sinf(th);
        size_t dbase = ((size_t)bh * S + s) * HD;
        float q1 = __half2float(p[tx]), q2 = __half2float(p[tx + 32]);
        g_qTh[dbase + tx]      = __float2half_rn((q1 * c - q2 * sn) * 0.125f);
        g_qTh[dbase + tx + 32] = __float2half_rn((q2 * c + q1 * sn) * 0.125f);
        float k1 = __half2float(p[64 + tx]), k2 = __half2float(p[64 + tx + 32]);
        g_kTh[dbase + tx]      = __float2half_rn(k1 * c - k2 * sn);
        g_kTh[dbase + tx + 32] = __float2half_rn(k2 * c + k1 * sn);
        vs[r][tx]      = p[128 + tx];
        vs[r][tx + 32] = p[128 + tx + 32];
    }
    __syncthreads();
    for (int d = ty; d < HD; d += 8)
        g_vTh[((size_t)bh * HD + d) * S + s0 + tx] = vs[tx][d];
}

// ---------------- fp16 tensor-core GEMM, 3-stage cp.async, ldmatrix --------
#define BM 128
#define BN 128
#define BK 32
#define ASTR 40
#define GEMM_SMEM (3 * (BM*ASTR + BN*ASTR) * 2)   /* 61440 B */

template<int MODE>
__global__ void __launch_bounds__(256) gemm_f16(
    const __half* __restrict__ A, const __half* __restrict__ WT,
    void* __restrict__ CoutV, int M, int N, int K)
{
    extern __shared__ __half hsm[];
    __half* AsP = hsm;
    __half* BsP = hsm + 3 * BM * ASTR;
    __shared__ int rt_s[BM];

    int e = blockIdx.z;
    int c = M;
    int r0 = blockIdx.y * BM;
    if (MODE == 1 || MODE == 2) {
        c = g_cnt[e];
        if (r0 >= c) return;
    }
    int col0 = blockIdx.x * BN;
    int tid = threadIdx.x;

    const __half* Ab = A;
    const __half* Wb = WT;
    if (MODE == 1) { Wb = WT + (size_t)e * N * K; }
    if (MODE == 2) { Ab = A + (size_t)e * T * K; Wb = WT + (size_t)e * N * K; }

    if (MODE == 1) {
        if (tid < BM) {
            int r = r0 + tid;
            rt_s[tid] = (r < c) ? g_tok[e * T + r] : 0;
        }
        __syncthreads();
    }

    int lane = tid & 31, warp = tid >> 5;
    int wm = warp >> 2, wn = warp & 3;
    int g = lane >> 2, cq = lane & 3;

    // ldmatrix per-thread byte offsets
    uint32_t AsU = smem_u32(AsP), BsU = smem_u32(BsP);
    const uint32_t aThr = 2u * ((uint32_t)(wm * 64 + (lane & 15)) * ASTR + (lane >> 4) * 8);
    uint32_t bThr[2];
#pragma unroll
    for (int j = 0; j < 2; j++)
        bThr[j] = 2u * ((uint32_t)(wn * 32 + (2 * j + (lane >> 4)) * 8 + (lane & 7)) * ASTR
                        + ((lane >> 3) & 1) * 8);

    auto issueA = [&](int stage, int k0) {
        __half* dst = AsP + stage * BM * ASTR;
#pragma unroll
        for (int i = 0; i < 2; i++) {
            int lin = tid + i * 256;
            int r = lin >> 2, ch = lin & 3;
            const __half* src;
            if (MODE == 1) src = Ab + (size_t)rt_s[r] * K + k0 + ch * 8;
            else           src = Ab + (size_t)(r0 + r) * K + k0 + ch * 8;
            cp_async16(dst + r * ASTR + ch * 8, src);
        }
    };
    auto issueB = [&](int stage, int k0) {
        __half* dst = BsP + stage * BN * ASTR;
#pragma unroll
        for (int i = 0; i < 2; i++) {
            int lin = tid + i * 256;
            int r = lin >> 2, ch = lin & 3;
            cp_async16(dst + r * ASTR + ch * 8, Wb + (size_t)(col0 + r) * K + k0 + ch * 8);
        }
    };

    float acc[4][4][4];
#pragma unroll
    for (int i = 0; i < 4; i++)
#pragma unroll
        for (int j = 0; j < 4; j++)
#pragma unroll
            for (int k = 0; k < 4; k++) acc[i][j][k] = 0.f;

    int nIter = K / BK;
    issueA(0, 0); issueB(0, 0); CP_COMMIT;
    issueA(1, BK); issueB(1, BK); CP_COMMIT;
    int cur = 0;

    for (int it = 0; it < nIter; it++) {
        if (it < nIter - 1) { CP_WAIT1; } else { CP_WAIT0; }
        __syncthreads();
        if (it + 2 < nIter) {
            int st = (it + 2) % 3;
            issueA(st, (it + 2) * BK);
            issueB(st, (it + 2) * BK);
            CP_COMMIT;
        }
        uint32_t stA = AsU + cur * (BM * ASTR * 2);
        uint32_t stB = BsU + cur * (BN * ASTR * 2);
#pragma unroll
        for (int kk = 0; kk < BK; kk += 16) {
            uint32_t a[4][4], b[4][2];
#pragma unroll
            for (int mt = 0; mt < 4; mt++)
                ldsm_x4(a[mt][0], a[mt][1], a[mt][2], a[mt][3],
                        stA + mt * (16 * ASTR * 2) + aThr + kk * 2);
#pragma unroll
            for (int j = 0; j < 2; j++)
                ldsm_x4(b[2*j][0], b[2*j][1], b[2*j+1][0], b[2*j+1][1],
                        stB + bThr[j] + kk * 2);
#pragma unroll
            for (int mt = 0; mt < 4; mt++)
#pragma unroll
                for (int nt = 0; nt < 4; nt++) {
                    MMA_F16(acc[mt][nt][0], acc[mt][nt][1], acc[mt][nt][2], acc[mt][nt][3],
                            a[mt][0], a[mt][1], a[mt][2], a[mt][3],
                            b[nt][0], b[nt][1]);
                }
        }
        cur = (cur + 1) % 3;
    }

    float* Cf = (float*)CoutV;
    __half* Ch = (__half*)CoutV;
#pragma unroll
    for (int mt = 0; mt < 4; mt++) {
#pragma unroll
        for (int nt = 0; nt < 4; nt++) {
#pragma unroll
            for (int hf = 0; hf < 2; hf++) {
                int lrow = wm * 64 + mt * 16 + g + hf * 8;
                int col = col0 + wn * 32 + nt * 8 + cq * 2;
                float v0 = acc[mt][nt][hf * 2 + 0];
                float v1 = acc[mt][nt][hf * 2 + 1];
                if (MODE == 0) {
                    Cf[(size_t)(r0 + lrow) * N + col]     = v0;
                    Cf[(size_t)(r0 + lrow) * N + col + 1] = v1;
                } else if (MODE == 3) {
                    Ch[(size_t)(r0 + lrow) * N + col]     = __float2half_rn(v0);
                    Ch[(size_t)(r0 + lrow) * N + col + 1] = __float2half_rn(v1);
                } else if (MODE == 1) {
                    int r = r0 + lrow;
                    if (r < c) {
                        float g0 = 0.5f * v0 * (1.f + erff(v0 * 0.70710678118f));
                        float g1 = 0.5f * v1 * (1.f + erff(v1 * 0.70710678118f));
                        g_hmid[((size_t)e * T + r) * F + col]     = __float2half_rn(g0);
                        g_hmid[((size_t)e * T + r) * F + col + 1] = __float2half_rn(g1);
                    }
                } else {
                    int r = r0 + lrow;
                    if (r < c) {
                        g_ybuf[((size_t)e * T + r) * H + col]     = v0;
                        g_ybuf[((size_t)e * T + r) * H + col + 1] = v1;
                    }
                }
            }
        }
    }
}

// ---------------- flash attention v7: fp16 MMA + ldmatrix B-frags ----------
#define KSH 72
#define VSH 72
#define FLASH_SMEM ((2*64*KSH + 2*64*VSH) * 2 + 2 * 64 * 4)

__global__ void __launch_bounds__(256) flash7_kernel(const int* __restrict__ mask) {
    extern __shared__ __half hfs[];
    __half* Kb = hfs;
    __half* Vb = Kb + 2 * 64 * KSH;
    int*    Mb = (int*)(Vb + 2 * 64 * VSH);

    int tid = threadIdx.x;
    int lane = tid & 31, warp = tid >> 5;
    int g = lane >> 2, cq = lane & 3;
    int q0 = blockIdx.x * 128, h = blockIdx.y, b = blockIdx.z;
    size_t bh = (size_t)(b * NH + h) * S;

    uint32_t qf[4][4];
    {
        const __half* qr0 = g_qTh + (bh + q0 + warp * 16 + g) * HD;
        const __half* qr1 = qr0 + 8 * HD;
#pragma unroll
        for (int cc = 0; cc < 4; cc++) {
            qf[cc][0] = *(const uint32_t*)(qr0 + cc * 16 + 2 * cq);
            qf[cc][1] = *(const uint32_t*)(qr1 + cc * 16 + 2 * cq);
            qf[cc][2] = *(const uint32_t*)(qr0 + cc * 16 + 2 * cq + 8);
            qf[cc][3] = *(const uint32_t*)(qr1 + cc * 16 + 2 * cq + 8);
        }
    }

    // ldmatrix per-thread offsets for K/V B-fragments
    uint32_t KbU = smem_u32(Kb), VbU = smem_u32(Vb);
    uint32_t kThr[4], vThr[4];
#pragma unroll
    for (int j = 0; j < 4; j++) {
        uint32_t row = (2 * j + (lane >> 4)) * 8 + (lane & 7);
        uint32_t col = ((lane >> 3) & 1) * 8;
        kThr[j] = 2u * (row * KSH + col);
        vThr[j] = 2u * (row * VSH + col);
    }

    auto issueKV = [&](int buf, int k0) {
#pragma unroll
        for (int i = 0; i < 4; i++) {
            int lin = tid + i * 256;
            int row = lin >> 3, ch = lin & 7;
            if (row < 64) {
                const __half* src = g_kTh + (bh + k0 + row) * HD + ch * 8;
                cp_async16(Kb + buf * 64 * KSH + row * KSH + ch * 8, src);
            } else {
                int d = row - 64;
                const __half* src = g_vTh + ((size_t)(b * NH + h) * HD + d) * S + k0 + ch * 8;
                cp_async16(Vb + buf * 64 * VSH + d * VSH + ch * 8, src);
            }
        }
        if (tid < 16)
            cp_async16(Mb + buf * 64 + tid * 4, mask + b * S + k0 + tid * 4);
    };

    float acc_o[8][4];
#pragma unroll
    for (int nt = 0; nt < 8; nt++)
#pragma unroll
        for (int j = 0; j < 4; j++) acc_o[nt][j] = 0.f;
    float m0r = -1e30f, m1r = -1e30f, l0 = 0.f, l1 = 0.f;

    uint32_t fullm = 0xffffffffu;

    issueKV(0, 0);
    CP_COMMIT;
    int cur = 0;

    for (int k0 = 0; k0 < S; k0 += 64) {
        CP_WAIT0;
        __syncthreads();
        if (k0 + 64 < S) {
            issueKV(cur ^ 1, k0 + 64);
            CP_COMMIT;
        }
        uint32_t Kcur = KbU + cur * (64 * KSH * 2);
        uint32_t Vcur = VbU + cur * (64 * VSH * 2);
        const int* Mc = Mb + cur * 64;

        float sacc[8][4];
#pragma unroll
        for (int nt = 0; nt < 8; nt++)
#pragma unroll
            for (int j = 0; j < 4; j++) sacc[nt][j] = 0.f;
#pragma unroll
        for (int cc = 0; cc < 4; cc++) {
            int kk = cc * 16;
            uint32_t bk[8][2];
#pragma unroll
            for (int j = 0; j < 4; j++)
                ldsm_x4(bk[2*j][0], bk[2*j][1], bk[2*j+1][0], bk[2*j+1][1],
                        Kcur + kThr[j] + kk * 2);
#pragma unroll
            for (int nt = 0; nt < 8; nt++) {
                MMA_F16(sacc[nt][0], sacc[nt][1], sacc[nt][2], sacc[nt][3],
                        qf[cc][0], qf[cc][1], qf[cc][2], qf[cc][3],
                        bk[nt][0], bk[nt][1]);
            }
        }

        float mx0 = -1e30f, mx1 = -1e30f;
#pragma unroll
        for (int nt = 0; nt < 8; nt++) {
            float mk0 = (Mc[nt * 8 + cq * 2]     == 0) ? -1e30f : 0.f;
            float mk1 = (Mc[nt * 8 + cq * 2 + 1] == 0) ? -1e30f : 0.f;
            sacc[nt][0] += mk0; sacc[nt][1] += mk1;
            sacc[nt][2] += mk0; sacc[nt][3] += mk1;
            mx0 = fmaxf(mx0, fmaxf(sacc[nt][0], sacc[nt][1]));
            mx1 = fmaxf(mx1, fmaxf(sacc[nt][2], sacc[nt][3]));
        }
        mx0 = fmaxf(mx0, __shfl_xor_sync(fullm, mx0, 1));
        mx0 = fmaxf(mx0, __shfl_xor_sync(fullm, mx0, 2));
        mx1 = fmaxf(mx1, __shfl_xor_sync(fullm, mx1, 1));
        mx1 = fmaxf(mx1, __shfl_xor_sync(fullm, mx1, 2));
        float newm0 = fmaxf(m0r, mx0), newm1 = fmaxf(m1r, mx1);
        float sc0 = __expf(m0r - newm0), sc1 = __expf(m1r - newm1);
        m0r = newm0; m1r = newm1;
        float ps0 = 0.f, ps1 = 0.f;
#pragma unroll
        for (int nt = 0; nt < 8; nt++) {
            sacc[nt][0] = __expf(sacc[nt][0] - newm0);
            sacc[nt][1] = __expf(sacc[nt][1] - newm0);
            sacc[nt][2] = __expf(sacc[nt][2] - newm1);
            sacc[nt][3] = __expf(sacc[nt][3] - newm1);
            ps0 += sacc[nt][0] + sacc[nt][1];
            ps1 += sacc[nt][2] + sacc[nt][3];
            acc_o[nt][0] *= sc0; acc_o[nt][1] *= sc0;
            acc_o[nt][2] *= sc1; acc_o[nt][3] *= sc1;
        }
        ps0 += __shfl_xor_sync(fullm, ps0, 1); ps0 += __shfl_xor_sync(fullm, ps0, 2);
        ps1 += __shfl_xor_sync(fullm, ps1, 1); ps1 += __shfl_xor_sync(fullm, ps1, 2);
        l0 = l0 * sc0 + ps0;
        l1 = l1 * sc1 + ps1;

#pragma unroll
        for (int kt = 0; kt < 4; kt++) {
            uint32_t a0 = h2_u32(sacc[2*kt][0],   sacc[2*kt][1]);
            uint32_t a1 = h2_u32(sacc[2*kt][2],   sacc[2*kt][3]);
            uint32_t a2 = h2_u32(sacc[2*kt+1][0], sacc[2*kt+1][1]);
            uint32_t a3 = h2_u32(sacc[2*kt+1][2], sacc[2*kt+1][3]);
            int kk = kt * 16;
            uint32_t bv[8][2];
#pragma unroll
            for (int j = 0; j < 4; j++)
                ldsm_x4(bv[2*j][0], bv[2*j][1], bv[2*j+1][0], bv[2*j+1][1],
                        Vcur + vThr[j] + kk * 2);
#pragma unroll
            for (int nt = 0; nt < 8; nt++) {
                MMA_F16(acc_o[nt][0], acc_o[nt][1], acc_o[nt][2], acc_o[nt][3],
                        a0, a1, a2, a3, bv[nt][0], bv[nt][1]);
            }
        }
        cur ^= 1;
    }

    float inv0 = 1.f / l0, inv1 = 1.f / l1;
    size_t row0 = (size_t)(b * S + q0 + warp * 16 + g) * H + h * HD;
    size_t row1 = row0 + (size_t)8 * H;
#pragma unroll
    for (int nt = 0; nt < 8; nt++) {
        int col = nt * 8 + cq * 2;
        g_ctx[row0 + col]     = __float2half_rn(acc_o[nt][0] * inv0);
        g_ctx[row0 + col + 1] = __float2half_rn(acc_o[nt][1] * inv0);
        g_ctx[row1 + col]     = __float2half_rn(acc_o[nt][2] * inv1);
        g_ctx[row1 + col + 1] = __float2half_rn(acc_o[nt][3] * inv1);
    }
}

// ---------------- fused: residual add + RMSNorm + router -------------------
__global__ void addnorm_router(const float* __restrict__ a, const float* __restrict__ bb,
                               const float* __restrict__ w,
                               const float* __restrict__ gate_w,
                               float* __restrict__ out, __half* __restrict__ out_h) {
    __shared__ float buf[H];
    __shared__ float red[8];
    __shared__ float logits[E];
    int t = blockIdx.x, tid = threadIdx.x;
    int lane = tid & 31, warp = tid >> 5;
    float ss = 0.f;
    for (int d = tid; d < H; d += 256) {
        float v = a[(size_t)t * H + d] + bb[(size_t)t * H + d];
        buf[d] = v;
        ss += v * v;
    }
    for (int o = 16; o; o >>= 1) ss += __shfl_xor_sync(~0u, ss, o);
    if (lane == 0) red[warp] = ss;
    __syncthreads();
    if (tid < 8) {
        float x = red[tid];
        for (int o = 4; o; o >>= 1) x += __shfl_xor_sync(0xffu, x, o);
        if (tid == 0) red[0] = x;
    }
    __syncthreads();
    float inv = rsqrtf(red[0] / (float)H + 1.1920929e-7f);
    for (int d = tid; d < H; d += 256) {
        float v = buf[d] * inv * w[d];
        out[(size_t)t * H + d] = v;
        out_h[(size_t)t * H + d] = __float2half_rn(v);
        buf[d] = v;
    }
    __syncthreads();
    {
        int e = warp;
        float acc = 0.f;
        for (int d = lane; d < H; d += 32)
            acc += buf[d] * gate_w[(size_t)d * E + e];
        for (int o = 16; o; o >>= 1) acc += __shfl_xor_sync(~0u, acc, o);
        if (lane == 0) logits[e] = acc;
    }
    __syncthreads();
    if (tid == 0) {
        float mx = logits[0];
#pragma unroll
        for (int e = 1; e < E; e++) mx = fmaxf(mx, logits[e]);
        float p[E]; float sum = 0.f;
#pragma unroll
        for (int e = 0; e < E; e++) { p[e] = expf(logits[e] - mx); sum += p[e]; }
        float pinv = 1.f / sum;
#pragma unroll
        for (int e = 0; e < E; e++) p[e] *= pinv;
        int i1 = 0;
#pragma unroll
        for (int e = 1; e < E; e++) if (p[e] > p[i1]) i1 = e;
        int i2 = -1;
#pragma unroll
        for (int e = 0; e < E; e++) {
            if (e == i1) continue;
            if (i2 < 0 || p[e] > p[i2]) i2 = e;
        }
        float s2 = p[i1] + p[i2];
        float w1n = p[i1] / s2, w2n = p[i2] / s2;
        int pos = atomicAdd(&g_cnt[i1], 1);
        g_tok[i1 * T + pos] = t;
        g_slot[t * 2] = i1 * T + pos;
        g_slotw[t * 2] = w1n;
        pos = atomicAdd(&g_cnt[i2], 1);
        g_tok[i2 * T + pos] = t;
        g_slot[t * 2 + 1] = i2 * T + pos;
        g_slotw[t * 2 + 1] = w2n;
#pragma unroll
        for (int e = 0; e < E; e++) atomicAdd(&g_probsum[e], p[e]);
    }
}

// ---------------- MoE combine + residual + RMSNorm (+ aux in block 0) ------
__global__ void moe_combine_norm(const float* __restrict__ w, float* __restrict__ out,
                                 float* __restrict__ aux_out) {
    __shared__ float buf[H];
    __shared__ float red[8];
    int t = blockIdx.x, tid = threadIdx.x;
    if (t == 0 && tid == 0) {
        float a = 0.f;
        for (int e = 0; e < E; e++)
            a += ((float)g_cnt[e] / (float)T) * (g_probsum[e] / (float)T);
        aux_out[0] = (float)E * a;
    }
    int s0 = g_slot[t * 2], s1 = g_slot[t * 2 + 1];
    float w0 = g_slotw[t * 2], w1v = g_slotw[t * 2 + 1];
    float ss = 0.f;
    for (int d = tid; d < H; d += 256) {
        float v = g_x1[(size_t)t * H + d]
                + w0 * g_ybuf[(size_t)s0 * H + d]
                + w1v * g_ybuf[(size_t)s1 * H + d];
        buf[d] = v;
        ss += v * v;
    }
    for (int o = 16; o; o >>= 1) ss += __shfl_xor_sync(~0u, ss, o);
    if ((tid & 31) == 0) red[tid >> 5] = ss;
    __syncthreads();
    if (tid < 8) {
        float x = red[tid];
        for (int o = 4; o; o >>= 1) x += __shfl_xor_sync(0xffu, x, o);
        if (tid == 0) red[0] = x;
    }
    __syncthreads();
    float inv = rsqrtf(red[0] / (float)H + 1.1920929e-7f);
    for (int d = tid; d < H; d += 256)
        out[(size_t)t * H + d] = buf[d] * inv * w[d];
}

// ---------------------------------------------------------------------------
extern "C" void kernel_launch(void* const* d_in, const int* in_sizes, int n_in,
                              void* d_out, int out_size) {
    const float* x      = (const float*)d_in[0];
    const int*   mask   = (const int*)  d_in[1];
    const float* qkv_w  = (const float*)d_in[2];
    const float* out_w  = (const float*)d_in[3];
    const float* gate_w = (const float*)d_in[4];
    const float* w1     = (const float*)d_in[5];
    const float* w2     = (const float*)d_in[6];
    const float* n1     = (const float*)d_in[7];
    const float* n2     = (const float*)d_in[8];
    float* out = (float*)d_out;

    float *p_attn, *p_x1;
    __half *p_qkv, *p_xt, *p_ctx, *p_x1t, *p_hmid;
    __half *p_qkvwT, *p_outwT, *p_w1T, *p_w2T;
    cudaGetSymbolAddress((void**)&p_qkv,   g_qkv);
    cudaGetSymbolAddress((void**)&p_ctx,   g_ctx);
    cudaGetSymbolAddress((void**)&p_attn,  g_attn);
    cudaGetSymbolAddress((void**)&p_x1,    g_x1);
    cudaGetSymbolAddress((void**)&p_x1t,   g_x1t);
    cudaGetSymbolAddress((void**)&p_xt,    g_xt);
    cudaGetSymbolAddress((void**)&p_hmid,  g_hmid);
    cudaGetSymbolAddress((void**)&p_qkvwT, g_qkvwT);
    cudaGetSymbolAddress((void**)&p_outwT, g_outwT);
    cudaGetSymbolAddress((void**)&p_w1T,   g_w1T);
    cudaGetSymbolAddress((void**)&p_w2T,   g_w2T);

    static bool attr_set = false;
    if (!attr_set) {
        cudaFuncSetAttribute(flash7_kernel,
                             cudaFuncAttributeMaxDynamicSharedMemorySize, FLASH_SMEM);
        cudaFuncSetAttribute(gemm_f16<0>,
                             cudaFuncAttributeMaxDynamicSharedMemorySize, GEMM_SMEM);
        cudaFuncSetAttribute(gemm_f16<1>,
                             cudaFuncAttributeMaxDynamicSharedMemorySize, GEMM_SMEM);
        cudaFuncSetAttribute(gemm_f16<2>,
                             cudaFuncAttributeMaxDynamicSharedMemorySize, GEMM_SMEM);
        cudaFuncSetAttribute(gemm_f16<3>,
                             cudaFuncAttributeMaxDynamicSharedMemorySize, GEMM_SMEM);
        attr_set = true;
    }

    half_copy_init<<<(T * H + 255) / 256, 256>>>(x, p_xt, T * H);
    transpose_half<<<dim3(H3 / 32, H / 32, 1), dim3(32, 8)>>>(qkv_w, p_qkvwT, H, H3);
    gemm_f16<3><<<dim3(H3 / BN, T / BM, 1), 256, GEMM_SMEM>>>(p_xt, p_qkvwT, p_qkv, T, H3, H);
    ropev_kernel<<<dim3(S / 32, B * NH), dim3(32, 8)>>>();
    flash7_kernel<<<dim3(S / 128, NH, B), 256, FLASH_SMEM>>>(mask);

    transpose_half<<<dim3(H / 32, H / 32, 1),  dim3(32, 8)>>>(out_w, p_outwT, H, H);
    gemm_f16<0><<<dim3(H / BN, T / BM, 1), 256, GEMM_SMEM>>>(p_ctx, p_outwT, p_attn, T, H, H);

    addnorm_router<<<T, 256>>>(x, p_attn, n1, gate_w, p_x1, p_x1t);

    transpose_half<<<dim3(F / 32, H / 32, E),  dim3(32, 8)>>>(w1, p_w1T, H, F);
    gemm_f16<1><<<dim3(F / BN, T / BM, E), 256, GEMM_SMEM>>>(p_x1t, p_w1T, nullptr, T, F, H);

    transpose_half<<<dim3(H / 32, F / 32, E),  dim3(32, 8)>>>(w2, p_w2T, F, H);
    gemm_f16<2><<<dim3(H / BN, T / BM, E), 256, GEMM_SMEM>>>(p_hmid, p_w2T, nullptr, T, H, F);

    moe_combine_norm<<<T, 256>>>(n2, out, out + (size_t)T * H);
}